// round 1
// baseline (speedup 1.0000x reference)
#include <cuda_runtime.h>
#include <math.h>

// ---------------- problem constants ----------------
#define B_SZ   2
#define SEQ    2048
#define DM     1024
#define DI     2048
#define DS     16
#define DTR    64
#define MROWS  (B_SZ * SEQ)      // 4096
#define E2     (2 * DI)          // 4096
#define XDBL_W 96                // DT_RANK + 2*D_STATE

// ---------------- scratch (device globals; no allocation allowed) ----------------
static __device__ float g_xz   [(size_t)MROWS * E2];    // [m][e]  e<DI: x_lin, e>=DI: z
static __device__ float g_x    [(size_t)MROWS * DI];    // post conv+silu, [m][d]
static __device__ float g_xdbl [(size_t)MROWS * XDBL_W];// [m][96]: dt_lo | B | C
static __device__ float g_delta[(size_t)MROWS * DI];    // [m][d]
static __device__ float g_y    [(size_t)MROWS * DI];    // [m][d] pre-out_proj

// ---------------- generic tiled fp32 GEMM:  C[M,N] = A[M,K] * B[N,K]^T ----------------
// BM=BN=128, BK=8, 256 threads, 8x8 microtile. Bounds-guarded (N=96 case).
// EPI==1: C = softplus(C + bias[col])
template<int EPI>
__global__ __launch_bounds__(256, 2)
void gemm_kernel(const float* __restrict__ A, int lda,
                 const float* __restrict__ Bw, int ldb,
                 float* __restrict__ C, int ldc,
                 int M, int N, int K,
                 const float* __restrict__ bias)
{
    __shared__ float As[8][128];
    __shared__ float Bs[8][128];

    const int tid = threadIdx.x;
    const int bm  = blockIdx.y * 128;
    const int bn  = blockIdx.x * 128;

    const int lrow = tid >> 1;        // 0..127 row within tile for loading
    const int lk4  = (tid & 1) * 4;   // 0 or 4

    const int tx   = tid & 15;
    const int ty   = tid >> 4;
    const int row0 = ty * 8;
    const int col0 = tx * 8;

    float acc[8][8];
#pragma unroll
    for (int i = 0; i < 8; i++)
#pragma unroll
        for (int j = 0; j < 8; j++) acc[i][j] = 0.f;

    for (int k0 = 0; k0 < K; k0 += 8) {
        // ---- load A tile (128 x 8), transposed store ----
        float4 av = make_float4(0.f, 0.f, 0.f, 0.f);
        {
            int ar = bm + lrow;
            if (ar < M)
                av = *reinterpret_cast<const float4*>(A + (size_t)ar * lda + k0 + lk4);
        }
        As[lk4 + 0][lrow] = av.x;
        As[lk4 + 1][lrow] = av.y;
        As[lk4 + 2][lrow] = av.z;
        As[lk4 + 3][lrow] = av.w;

        // ---- load B tile (128 x 8), transposed store ----
        float4 bv = make_float4(0.f, 0.f, 0.f, 0.f);
        {
            int br = bn + lrow;
            if (br < N)
                bv = *reinterpret_cast<const float4*>(Bw + (size_t)br * ldb + k0 + lk4);
        }
        Bs[lk4 + 0][lrow] = bv.x;
        Bs[lk4 + 1][lrow] = bv.y;
        Bs[lk4 + 2][lrow] = bv.z;
        Bs[lk4 + 3][lrow] = bv.w;

        __syncthreads();

#pragma unroll
        for (int kk = 0; kk < 8; kk++) {
            float a[8], b[8];
            *reinterpret_cast<float4*>(&a[0]) = *reinterpret_cast<const float4*>(&As[kk][row0]);
            *reinterpret_cast<float4*>(&a[4]) = *reinterpret_cast<const float4*>(&As[kk][row0 + 4]);
            *reinterpret_cast<float4*>(&b[0]) = *reinterpret_cast<const float4*>(&Bs[kk][col0]);
            *reinterpret_cast<float4*>(&b[4]) = *reinterpret_cast<const float4*>(&Bs[kk][col0 + 4]);
#pragma unroll
            for (int i = 0; i < 8; i++)
#pragma unroll
                for (int j = 0; j < 8; j++)
                    acc[i][j] = fmaf(a[i], b[j], acc[i][j]);
        }
        __syncthreads();
    }

    // ---- epilogue ----
#pragma unroll
    for (int i = 0; i < 8; i++) {
        int row = bm + row0 + i;
        if (row >= M) continue;
#pragma unroll
        for (int j = 0; j < 8; j++) {
            int col = bn + col0 + j;
            if (col >= N) continue;
            float v = acc[i][j];
            if (EPI == 1) {
                v += bias[col];
                v = (v > 20.f) ? v : log1pf(expf(v));   // softplus
            }
            C[(size_t)row * ldc + col] = v;
        }
    }
}

// ---------------- depthwise conv (width 4, causal) + bias + silu ----------------
// x_lin layout [m][e] (e < DI).  Output g_x[m][d].  Coalesced over d.
__global__ void conv_silu_kernel(const float* __restrict__ cw,
                                 const float* __restrict__ cb)
{
    int d = blockIdx.x * blockDim.x + threadIdx.x;   // 0..DI-1
    int m = blockIdx.y;                              // 0..MROWS-1
    int l = m & (SEQ - 1);

    float acc = cb[d];
#pragma unroll
    for (int k = 0; k < 4; k++) {
        int ll = l - 3 + k;
        if (ll >= 0)
            acc = fmaf(cw[d * 4 + k], g_xz[(size_t)(m - 3 + k) * E2 + d], acc);
    }
    float s = acc / (1.f + expf(-acc));              // silu
    g_x[(size_t)m * DI + d] = s;
}

// ---------------- selective scan (serial over L), fused D*x + silu(z) gating ----------------
// one thread per channel (b,d); h[16] in registers; B_t/C_t uniform float4 broadcasts.
__global__ void scan_kernel(const float* __restrict__ A_log,
                            const float* __restrict__ Dp)
{
    int chan = blockIdx.x * blockDim.x + threadIdx.x; // 0..4095
    if (chan >= B_SZ * DI) return;
    int b = chan >> 11;          // /DI
    int d = chan & (DI - 1);

    float Arow[DS];
#pragma unroll
    for (int n = 0; n < DS; n++) Arow[n] = -expf(A_log[d * DS + n]);
    float Dd = Dp[d];

    float h[DS];
#pragma unroll
    for (int n = 0; n < DS; n++) h[n] = 0.f;

    size_t mbase = (size_t)b * SEQ;
    for (int l = 0; l < SEQ; l++) {
        size_t m = mbase + l;
        float dt = g_delta[m * DI + d];
        float xv = g_x[m * DI + d];
        float zv = g_xz[m * E2 + DI + d];

        const float4* P = reinterpret_cast<const float4*>(g_xdbl + m * XDBL_W + DTR);
        float Bv[DS], Cv[DS];
#pragma unroll
        for (int i = 0; i < 4; i++) {
            float4 t = P[i];
            Bv[4 * i] = t.x; Bv[4 * i + 1] = t.y; Bv[4 * i + 2] = t.z; Bv[4 * i + 3] = t.w;
        }
#pragma unroll
        for (int i = 0; i < 4; i++) {
            float4 t = P[4 + i];
            Cv[4 * i] = t.x; Cv[4 * i + 1] = t.y; Cv[4 * i + 2] = t.z; Cv[4 * i + 3] = t.w;
        }

        float dx = dt * xv;
        float acc = 0.f;
#pragma unroll
        for (int n = 0; n < DS; n++) {
            float dA = __expf(dt * Arow[n]);
            h[n] = fmaf(dA, h[n], dx * Bv[n]);
            acc = fmaf(h[n], Cv[n], acc);
        }

        float sz = zv / (1.f + __expf(-zv));          // silu(z)
        g_y[m * DI + d] = (acc + Dd * xv) * sz;
    }
}

// ---------------- launch ----------------
extern "C" void kernel_launch(void* const* d_in, const int* in_sizes, int n_in,
                              void* d_out, int out_size)
{
    const float* hs        = (const float*)d_in[0];   // [B,L,DM]
    const float* in_proj_w = (const float*)d_in[1];   // [2*DI, DM]
    const float* conv_w    = (const float*)d_in[2];   // [DI, 4]
    const float* conv_b    = (const float*)d_in[3];   // [DI]
    const float* x_proj_w  = (const float*)d_in[4];   // [96, DI]
    const float* dt_proj_w = (const float*)d_in[5];   // [DI, 64]
    const float* dt_proj_b = (const float*)d_in[6];   // [DI]
    const float* A_log     = (const float*)d_in[7];   // [DI, 16]
    const float* Dp        = (const float*)d_in[8];   // [DI]
    const float* out_w     = (const float*)d_in[9];   // [DM, DI]
    float* out = (float*)d_out;                       // [B,L,DM]

    float *p_xz, *p_x, *p_xdbl, *p_delta, *p_y;
    cudaGetSymbolAddress((void**)&p_xz,    g_xz);
    cudaGetSymbolAddress((void**)&p_x,     g_x);
    cudaGetSymbolAddress((void**)&p_xdbl,  g_xdbl);
    cudaGetSymbolAddress((void**)&p_delta, g_delta);
    cudaGetSymbolAddress((void**)&p_y,     g_y);

    // K1: xz[m][e] = hs[m][:] . in_proj_w[e][:]      (4096 x 4096 x 1024)
    gemm_kernel<0><<<dim3(E2 / 128, MROWS / 128), 256>>>(
        hs, DM, in_proj_w, DM, p_xz, E2, MROWS, E2, DM, nullptr);

    // K2: depthwise conv + bias + silu
    conv_silu_kernel<<<dim3(DI / 256, MROWS), 256>>>(conv_w, conv_b);

    // K3: x_dbl[m][0:96] = x[m][:] . x_proj_w[e][:]  (4096 x 96 x 2048)
    gemm_kernel<0><<<dim3(1, MROWS / 128), 256>>>(
        p_x, DI, x_proj_w, DI, p_xdbl, XDBL_W, MROWS, XDBL_W, DI, nullptr);

    // K4: delta[m][d] = softplus(x_dbl[m][0:64] . dt_proj_w[d][:] + dt_b[d])
    gemm_kernel<1><<<dim3(DI / 128, MROWS / 128), 256>>>(
        p_xdbl, XDBL_W, dt_proj_w, DTR, p_delta, DI, MROWS, DI, DTR, dt_proj_b);

    // K5: selective scan + gating
    scan_kernel<<<128, 32>>>(A_log, Dp);

    // K6: out[m][mm] = y[m][:] . out_w[mm][:]        (4096 x 1024 x 2048)
    gemm_kernel<0><<<dim3(DM / 128, MROWS / 128), 256>>>(
        p_y, DI, out_w, DI, out, DM, MROWS, DM, DI, nullptr);
}

// round 2
// speedup vs baseline: 1.4302x; 1.4302x over previous
#include <cuda_runtime.h>
#include <cuda_bf16.h>
#include <math.h>
#include <stdint.h>

// ---------------- problem constants ----------------
#define B_SZ   2
#define SEQ    2048
#define DM     1024
#define DI     2048
#define DS     16
#define DTR    64
#define MROWS  (B_SZ * SEQ)      // 4096
#define E2     (2 * DI)          // 4096
#define XDBL_W 96                // DT_RANK + 2*D_STATE

// ---------------- scratch (device globals; no allocation allowed) ----------------
static __device__ float g_xz   [(size_t)MROWS * E2];    // [m][e]  e<DI: x_lin, e>=DI: z
static __device__ float g_x    [(size_t)MROWS * DI];    // post conv+silu, [m][d]
static __device__ float g_xdbl [(size_t)MROWS * XDBL_W];// [m][96]: dt_lo | B | C
static __device__ float g_delta[(size_t)MROWS * DI];    // [m][d]
static __device__ float g_y    [(size_t)MROWS * DI];    // [m][d] pre-out_proj

// ---------------- tensor-core helpers ----------------
__device__ __forceinline__ void ldsm_x4(uint32_t& r0, uint32_t& r1, uint32_t& r2, uint32_t& r3,
                                        const __nv_bfloat16* p)
{
    uint32_t addr = (uint32_t)__cvta_generic_to_shared(p);
    asm volatile("ldmatrix.sync.aligned.m8n8.x4.shared.b16 {%0,%1,%2,%3}, [%4];\n"
                 : "=r"(r0), "=r"(r1), "=r"(r2), "=r"(r3) : "r"(addr));
}

__device__ __forceinline__ void mma_bf16(float* c, const uint32_t* a, const uint32_t* b)
{
    asm volatile(
        "mma.sync.aligned.m16n8k16.row.col.f32.bf16.bf16.f32 "
        "{%0,%1,%2,%3}, {%4,%5,%6,%7}, {%8,%9}, {%0,%1,%2,%3};\n"
        : "+f"(c[0]), "+f"(c[1]), "+f"(c[2]), "+f"(c[3])
        : "r"(a[0]), "r"(a[1]), "r"(a[2]), "r"(a[3]), "r"(b[0]), "r"(b[1]));
}

// ---------------- bf16-split tensor-core GEMM:  C[M,N] = A[M,K] * B[N,K]^T ----------------
// 128x128x32 block tile, 8 warps (4 x 2), warp tile 32x64 (2x8 m16n8k16 fragments).
// Inputs fp32; decomposed a = a_hi + a_lo (bf16 each); acc = hi*hi + hi*lo + lo*hi in fp32.
// Requires K % 32 == 0, lda/ldb % 4 == 0, M % 128 == 0 (true for all call sites), N even.
// EPI==1: C = softplus(C + bias[col])
#define BK    32
#define LDSM_ (BK + 8)   // 40-element row stride: conflict-free ldmatrix banks

template<int EPI>
__global__ __launch_bounds__(256)
void gemm_tc(const float* __restrict__ A, int lda,
             const float* __restrict__ Bw, int ldb,
             float* __restrict__ C, int ldc,
             int M, int N, int K,
             const float* __restrict__ bias)
{
    __shared__ __nv_bfloat16 sAh[128][LDSM_];
    __shared__ __nv_bfloat16 sAl[128][LDSM_];
    __shared__ __nv_bfloat16 sBh[128][LDSM_];
    __shared__ __nv_bfloat16 sBl[128][LDSM_];

    const int tid  = threadIdx.x;
    const int lane = tid & 31;
    const int wid  = tid >> 5;
    const int wm   = wid & 3;      // warp row 0..3  (32 rows each)
    const int wn   = wid >> 2;     // warp col 0..1  (64 cols each)

    const int bm = blockIdx.y * 128;
    const int bn = blockIdx.x * 128;

    // loader coordinates: each thread: row = tid/8 (+32*p), 4 consecutive k at (tid%8)*4
    const int lr = tid >> 3;
    const int lc = (tid & 7) * 4;

    float acc[2][8][4];
#pragma unroll
    for (int i = 0; i < 2; i++)
#pragma unroll
        for (int j = 0; j < 8; j++)
#pragma unroll
            for (int q = 0; q < 4; q++) acc[i][j][q] = 0.f;

    for (int k0 = 0; k0 < K; k0 += BK) {
        // ---------- fill smem: fp32 -> (hi, lo) bf16 ----------
#pragma unroll
        for (int p = 0; p < 4; p++) {
            int r = lr + p * 32;
            // A tile
            {
                float4 v = *reinterpret_cast<const float4*>(A + (size_t)(bm + r) * lda + k0 + lc);
                __nv_bfloat16 h0 = __float2bfloat16(v.x);
                __nv_bfloat16 h1 = __float2bfloat16(v.y);
                __nv_bfloat16 h2 = __float2bfloat16(v.z);
                __nv_bfloat16 h3 = __float2bfloat16(v.w);
                __nv_bfloat162 hh0; hh0.x = h0; hh0.y = h1;
                __nv_bfloat162 hh1; hh1.x = h2; hh1.y = h3;
                *reinterpret_cast<__nv_bfloat162*>(&sAh[r][lc])     = hh0;
                *reinterpret_cast<__nv_bfloat162*>(&sAh[r][lc + 2]) = hh1;
                __nv_bfloat162 ll0, ll1;
                ll0.x = __float2bfloat16(v.x - __bfloat162float(h0));
                ll0.y = __float2bfloat16(v.y - __bfloat162float(h1));
                ll1.x = __float2bfloat16(v.z - __bfloat162float(h2));
                ll1.y = __float2bfloat16(v.w - __bfloat162float(h3));
                *reinterpret_cast<__nv_bfloat162*>(&sAl[r][lc])     = ll0;
                *reinterpret_cast<__nv_bfloat162*>(&sAl[r][lc + 2]) = ll1;
            }
            // B tile (guard N: rows >= N are zero)
            {
                float4 v = make_float4(0.f, 0.f, 0.f, 0.f);
                int br = bn + r;
                if (br < N)
                    v = *reinterpret_cast<const float4*>(Bw + (size_t)br * ldb + k0 + lc);
                __nv_bfloat16 h0 = __float2bfloat16(v.x);
                __nv_bfloat16 h1 = __float2bfloat16(v.y);
                __nv_bfloat16 h2 = __float2bfloat16(v.z);
                __nv_bfloat16 h3 = __float2bfloat16(v.w);
                __nv_bfloat162 hh0; hh0.x = h0; hh0.y = h1;
                __nv_bfloat162 hh1; hh1.x = h2; hh1.y = h3;
                *reinterpret_cast<__nv_bfloat162*>(&sBh[r][lc])     = hh0;
                *reinterpret_cast<__nv_bfloat162*>(&sBh[r][lc + 2]) = hh1;
                __nv_bfloat162 ll0, ll1;
                ll0.x = __float2bfloat16(v.x - __bfloat162float(h0));
                ll0.y = __float2bfloat16(v.y - __bfloat162float(h1));
                ll1.x = __float2bfloat16(v.z - __bfloat162float(h2));
                ll1.y = __float2bfloat16(v.w - __bfloat162float(h3));
                *reinterpret_cast<__nv_bfloat162*>(&sBl[r][lc])     = ll0;
                *reinterpret_cast<__nv_bfloat162*>(&sBl[r][lc + 2]) = ll1;
            }
        }
        __syncthreads();

        // ---------- compute: 2 k16 steps ----------
#pragma unroll
        for (int ks = 0; ks < 2; ks++) {
            // A fragments: row = base + (lane & 15), k = ks*16 + (lane>>4)*8
            uint32_t ah[2][4], al[2][4];
            {
                int arow_off = (lane & 15);
                int akc = ks * 16 + (lane >> 4) * 8;
#pragma unroll
                for (int mt = 0; mt < 2; mt++) {
                    int arow = wm * 32 + mt * 16 + arow_off;
                    ldsm_x4(ah[mt][0], ah[mt][1], ah[mt][2], ah[mt][3], &sAh[arow][akc]);
                    ldsm_x4(al[mt][0], al[mt][1], al[mt][2], al[mt][3], &sAl[arow][akc]);
                }
            }
            // B fragments: n = base + (lane&7) + ((lane>>4)&1)*8, k = ks*16 + ((lane>>3)&1)*8
            uint32_t bh[8][2], bl[8][2];
            {
                int nrow_off = (lane & 7) + ((lane >> 4) & 1) * 8;
                int bkc = ks * 16 + ((lane >> 3) & 1) * 8;
#pragma unroll
                for (int ntp = 0; ntp < 4; ntp++) {
                    int nrow = wn * 64 + ntp * 16 + nrow_off;
                    ldsm_x4(bh[2 * ntp][0], bh[2 * ntp][1], bh[2 * ntp + 1][0], bh[2 * ntp + 1][1],
                            &sBh[nrow][bkc]);
                    ldsm_x4(bl[2 * ntp][0], bl[2 * ntp][1], bl[2 * ntp + 1][0], bl[2 * ntp + 1][1],
                            &sBl[nrow][bkc]);
                }
            }
#pragma unroll
            for (int mt = 0; mt < 2; mt++)
#pragma unroll
                for (int nt = 0; nt < 8; nt++) {
                    mma_bf16(acc[mt][nt], ah[mt], bh[nt]);   // hi * hi
                    mma_bf16(acc[mt][nt], ah[mt], bl[nt]);   // hi * lo
                    mma_bf16(acc[mt][nt], al[mt], bh[nt]);   // lo * hi
                }
        }
        __syncthreads();
    }

    // ---------- epilogue ----------
#pragma unroll
    for (int mt = 0; mt < 2; mt++) {
        int row = bm + wm * 32 + mt * 16 + (lane >> 2);
#pragma unroll
        for (int nt = 0; nt < 8; nt++) {
            int col = bn + wn * 64 + nt * 8 + (lane & 3) * 2;
            if (col >= N) continue;
#pragma unroll
            for (int half = 0; half < 2; half++) {
                int r = row + half * 8;
                float v0 = acc[mt][nt][2 * half + 0];
                float v1 = acc[mt][nt][2 * half + 1];
                if (EPI == 1) {
                    v0 += bias[col];
                    v1 += bias[col + 1];
                    v0 = (v0 > 20.f) ? v0 : log1pf(expf(v0));
                    v1 = (v1 > 20.f) ? v1 : log1pf(expf(v1));
                }
                float2 st; st.x = v0; st.y = v1;
                *reinterpret_cast<float2*>(C + (size_t)r * ldc + col) = st;
            }
        }
    }
}

// ---------------- depthwise conv (width 4, causal) + bias + silu ----------------
__global__ void conv_silu_kernel(const float* __restrict__ cw,
                                 const float* __restrict__ cb)
{
    int d = blockIdx.x * blockDim.x + threadIdx.x;   // 0..DI-1
    int m = blockIdx.y;                              // 0..MROWS-1
    int l = m & (SEQ - 1);

    float acc = cb[d];
#pragma unroll
    for (int k = 0; k < 4; k++) {
        int ll = l - 3 + k;
        if (ll >= 0)
            acc = fmaf(cw[d * 4 + k], g_xz[(size_t)(m - 3 + k) * E2 + d], acc);
    }
    float s = acc / (1.f + expf(-acc));              // silu
    g_x[(size_t)m * DI + d] = s;
}

// ---------------- selective scan (serial over L), fused D*x + silu(z) gating ----------------
__global__ void scan_kernel(const float* __restrict__ A_log,
                            const float* __restrict__ Dp)
{
    int chan = blockIdx.x * blockDim.x + threadIdx.x; // 0..4095
    if (chan >= B_SZ * DI) return;
    int b = chan >> 11;          // /DI
    int d = chan & (DI - 1);

    float Arow[DS];
#pragma unroll
    for (int n = 0; n < DS; n++) Arow[n] = -expf(A_log[d * DS + n]);
    float Dd = Dp[d];

    float h[DS];
#pragma unroll
    for (int n = 0; n < DS; n++) h[n] = 0.f;

    size_t mbase = (size_t)b * SEQ;
    for (int l = 0; l < SEQ; l++) {
        size_t m = mbase + l;
        float dt = g_delta[m * DI + d];
        float xv = g_x[m * DI + d];
        float zv = g_xz[m * E2 + DI + d];

        const float4* P = reinterpret_cast<const float4*>(g_xdbl + m * XDBL_W + DTR);
        float Bv[DS], Cv[DS];
#pragma unroll
        for (int i = 0; i < 4; i++) {
            float4 t = P[i];
            Bv[4 * i] = t.x; Bv[4 * i + 1] = t.y; Bv[4 * i + 2] = t.z; Bv[4 * i + 3] = t.w;
        }
#pragma unroll
        for (int i = 0; i < 4; i++) {
            float4 t = P[4 + i];
            Cv[4 * i] = t.x; Cv[4 * i + 1] = t.y; Cv[4 * i + 2] = t.z; Cv[4 * i + 3] = t.w;
        }

        float dx = dt * xv;
        float acc = 0.f;
#pragma unroll
        for (int n = 0; n < DS; n++) {
            float dA = __expf(dt * Arow[n]);
            h[n] = fmaf(dA, h[n], dx * Bv[n]);
            acc = fmaf(h[n], Cv[n], acc);
        }

        float sz = zv / (1.f + __expf(-zv));          // silu(z)
        g_y[m * DI + d] = (acc + Dd * xv) * sz;
    }
}

// ---------------- launch ----------------
extern "C" void kernel_launch(void* const* d_in, const int* in_sizes, int n_in,
                              void* d_out, int out_size)
{
    const float* hs        = (const float*)d_in[0];   // [B,L,DM]
    const float* in_proj_w = (const float*)d_in[1];   // [2*DI, DM]
    const float* conv_w    = (const float*)d_in[2];   // [DI, 4]
    const float* conv_b    = (const float*)d_in[3];   // [DI]
    const float* x_proj_w  = (const float*)d_in[4];   // [96, DI]
    const float* dt_proj_w = (const float*)d_in[5];   // [DI, 64]
    const float* dt_proj_b = (const float*)d_in[6];   // [DI]
    const float* A_log     = (const float*)d_in[7];   // [DI, 16]
    const float* Dp        = (const float*)d_in[8];   // [DI]
    const float* out_w     = (const float*)d_in[9];   // [DM, DI]
    float* out = (float*)d_out;                       // [B,L,DM]

    float *p_xz, *p_x, *p_xdbl, *p_delta, *p_y;
    cudaGetSymbolAddress((void**)&p_xz,    g_xz);
    cudaGetSymbolAddress((void**)&p_x,     g_x);
    cudaGetSymbolAddress((void**)&p_xdbl,  g_xdbl);
    cudaGetSymbolAddress((void**)&p_delta, g_delta);
    cudaGetSymbolAddress((void**)&p_y,     g_y);

    // K1: xz[m][e] = hs[m][:] . in_proj_w[e][:]      (4096 x 4096 x 1024)
    gemm_tc<0><<<dim3(E2 / 128, MROWS / 128), 256>>>(
        hs, DM, in_proj_w, DM, p_xz, E2, MROWS, E2, DM, nullptr);

    // K2: depthwise conv + bias + silu
    conv_silu_kernel<<<dim3(DI / 256, MROWS), 256>>>(conv_w, conv_b);

    // K3: x_dbl[m][0:96] = x[m][:] . x_proj_w[e][:]  (4096 x 96 x 2048)
    gemm_tc<0><<<dim3(1, MROWS / 128), 256>>>(
        p_x, DI, x_proj_w, DI, p_xdbl, XDBL_W, MROWS, XDBL_W, DI, nullptr);

    // K4: delta[m][d] = softplus(x_dbl[m][0:64] . dt_proj_w[d][:] + dt_b[d])
    gemm_tc<1><<<dim3(DI / 128, MROWS / 128), 256>>>(
        p_xdbl, XDBL_W, dt_proj_w, DTR, p_delta, DI, MROWS, DI, DTR, dt_proj_b);

    // K5: selective scan + gating
    scan_kernel<<<128, 32>>>(A_log, Dp);

    // K6: out[m][mm] = y[m][:] . out_w[mm][:]        (4096 x 1024 x 2048)
    gemm_tc<0><<<dim3(DM / 128, MROWS / 128), 256>>>(
        p_y, DI, out_w, DI, out, DM, MROWS, DM, DI, nullptr);
}

// round 3
// speedup vs baseline: 2.2563x; 1.5777x over previous
#include <cuda_runtime.h>
#include <cuda_bf16.h>
#include <math.h>
#include <stdint.h>

// ---------------- problem constants ----------------
#define B_SZ   2
#define SEQ    2048
#define DM     1024
#define DI     2048
#define DS     16
#define DTR    64
#define MROWS  (B_SZ * SEQ)      // 4096
#define E2     (2 * DI)          // 4096
#define XDBL_W 96                // DT_RANK + 2*D_STATE

// ---------------- scratch (device globals; no allocation allowed) ----------------
static __device__ float g_xz   [(size_t)MROWS * E2];    // [m][e]  e<DI: x_lin, e>=DI: z
static __device__ float g_x    [(size_t)MROWS * DI];    // post conv+silu fp32 (scan)
static __device__ float g_xdbl [(size_t)MROWS * XDBL_W];// [m][96]: dt_lo | B | C
static __device__ float g_delta[(size_t)MROWS * DI];    // [m][d]

// bf16 hi/lo split buffers
static __device__ __nv_bfloat16 g_hs_h[(size_t)MROWS * DM];
static __device__ __nv_bfloat16 g_hs_l[(size_t)MROWS * DM];
static __device__ __nv_bfloat16 g_w1_h[(size_t)E2 * DM];
static __device__ __nv_bfloat16 g_w1_l[(size_t)E2 * DM];
static __device__ __nv_bfloat16 g_xp_h[(size_t)128 * DI];   // x_proj padded 96->128 rows
static __device__ __nv_bfloat16 g_xp_l[(size_t)128 * DI];
static __device__ __nv_bfloat16 g_ow_h[(size_t)DM * DI];
static __device__ __nv_bfloat16 g_ow_l[(size_t)DM * DI];
static __device__ __nv_bfloat16 g_xh  [(size_t)MROWS * DI]; // conv output bf16
static __device__ __nv_bfloat16 g_xl  [(size_t)MROWS * DI];
static __device__ __nv_bfloat16 g_yh  [(size_t)MROWS * DI]; // scan output bf16
static __device__ __nv_bfloat16 g_yl  [(size_t)MROWS * DI];

// ---------------- tensor-core helpers ----------------
__device__ __forceinline__ void ldsm_x4(uint32_t& r0, uint32_t& r1, uint32_t& r2, uint32_t& r3,
                                        const __nv_bfloat16* p)
{
    uint32_t addr = (uint32_t)__cvta_generic_to_shared(p);
    asm volatile("ldmatrix.sync.aligned.m8n8.x4.shared.b16 {%0,%1,%2,%3}, [%4];\n"
                 : "=r"(r0), "=r"(r1), "=r"(r2), "=r"(r3) : "r"(addr));
}

__device__ __forceinline__ void mma_bf16(float* c, const uint32_t* a, const uint32_t* b)
{
    asm volatile(
        "mma.sync.aligned.m16n8k16.row.col.f32.bf16.bf16.f32 "
        "{%0,%1,%2,%3}, {%4,%5,%6,%7}, {%8,%9}, {%0,%1,%2,%3};\n"
        : "+f"(c[0]), "+f"(c[1]), "+f"(c[2]), "+f"(c[3])
        : "r"(a[0]), "r"(a[1]), "r"(a[2]), "r"(a[3]), "r"(b[0]), "r"(b[1]));
}

__device__ __forceinline__ void cp16(__nv_bfloat16* dst, const __nv_bfloat16* src)
{
    uint32_t d = (uint32_t)__cvta_generic_to_shared(dst);
    asm volatile("cp.async.cg.shared.global [%0], [%1], 16;\n" :: "r"(d), "l"(src));
}
__device__ __forceinline__ void cp_commit() { asm volatile("cp.async.commit_group;\n"); }
template<int N>
__device__ __forceinline__ void cp_wait()   { asm volatile("cp.async.wait_group %0;\n" :: "n"(N)); }

// ---------------- fp32 -> bf16 hi/lo split conversion (vectorized, run each launch) ----
// n_total elements written; elements >= n_valid are zero (for row padding).
__global__ void cvt_kernel(const float* __restrict__ src,
                           __nv_bfloat16* __restrict__ hi,
                           __nv_bfloat16* __restrict__ lo,
                           int n_valid, int n_total)
{
    int i4 = (blockIdx.x * blockDim.x + threadIdx.x) * 4;
    if (i4 >= n_total) return;
    float4 v = make_float4(0.f, 0.f, 0.f, 0.f);
    if (i4 < n_valid) v = *reinterpret_cast<const float4*>(src + i4);
    __nv_bfloat16 h[4], l[4];
    float f[4] = {v.x, v.y, v.z, v.w};
#pragma unroll
    for (int j = 0; j < 4; j++) {
        h[j] = __float2bfloat16(f[j]);
        l[j] = __float2bfloat16(f[j] - __bfloat162float(h[j]));
    }
    *reinterpret_cast<uint2*>(hi + i4) = *reinterpret_cast<uint2*>(h);
    *reinterpret_cast<uint2*>(lo + i4) = *reinterpret_cast<uint2*>(l);
}

// ---------------- bf16-split tensor-core GEMM (pre-split inputs, cp.async 2-stage) ------
// C[M,N] = A[M,K] * B[N,K]^T ;  A,B given as bf16 hi/lo pairs.
// 128x128x32 block tile, 8 warps (4x2), warp tile 32x64 (2x8 m16n8k16 frags).
// M % 128 == 0; B buffers padded so rows bn..bn+127 always readable; store guarded col<N.
#define BK    32
#define LDSM_ 40                       // row stride (elems): conflict-free ldmatrix
#define TILE_ (128 * LDSM_)            // elems per tile
#define STAGE_ (4 * TILE_)             // 4 tiles per stage

__global__ __launch_bounds__(256)
void gemm_bf(const __nv_bfloat16* __restrict__ Ah, const __nv_bfloat16* __restrict__ Al, int lda,
             const __nv_bfloat16* __restrict__ Bh, const __nv_bfloat16* __restrict__ Bl, int ldb,
             float* __restrict__ C, int ldc,
             int M, int N, int K)
{
    extern __shared__ __nv_bfloat16 smem[];

    const int tid  = threadIdx.x;
    const int lane = tid & 31;
    const int wid  = tid >> 5;
    const int wm   = wid & 3;
    const int wn   = wid >> 2;

    const int bm = blockIdx.y * 128;
    const int bn = blockIdx.x * 128;

    // loader: row = tid>>2 (+64), 8 elems at col (tid&3)*8
    const int lr = tid >> 2;
    const int lc = (tid & 3) * 8;

    const __nv_bfloat16* srcA_h = Ah + (size_t)(bm + lr) * lda + lc;
    const __nv_bfloat16* srcA_l = Al + (size_t)(bm + lr) * lda + lc;
    const __nv_bfloat16* srcB_h = Bh + (size_t)(bn + lr) * ldb + lc;
    const __nv_bfloat16* srcB_l = Bl + (size_t)(bn + lr) * ldb + lc;

    float acc[2][8][4];
#pragma unroll
    for (int i = 0; i < 2; i++)
#pragma unroll
        for (int j = 0; j < 8; j++)
#pragma unroll
            for (int q = 0; q < 4; q++) acc[i][j][q] = 0.f;

    const int KT = K / BK;

    auto load_stage = [&](int s, int k0) {
        __nv_bfloat16* base = smem + s * STAGE_;
        __nv_bfloat16* dA_h = base;
        __nv_bfloat16* dA_l = base + TILE_;
        __nv_bfloat16* dB_h = base + 2 * TILE_;
        __nv_bfloat16* dB_l = base + 3 * TILE_;
#pragma unroll
        for (int p = 0; p < 2; p++) {
            int r = lr + p * 64;
            size_t so = (size_t)p * 64 * lda + k0;
            size_t so2 = (size_t)p * 64 * ldb + k0;
            cp16(dA_h + r * LDSM_ + lc, srcA_h + so);
            cp16(dA_l + r * LDSM_ + lc, srcA_l + so);
            cp16(dB_h + r * LDSM_ + lc, srcB_h + so2);
            cp16(dB_l + r * LDSM_ + lc, srcB_l + so2);
        }
    };

    load_stage(0, 0);
    cp_commit();

    for (int it = 0; it < KT; it++) {
        if (it + 1 < KT) {
            load_stage((it + 1) & 1, (it + 1) * BK);
            cp_commit();
            cp_wait<1>();
        } else {
            cp_wait<0>();
        }
        __syncthreads();

        const __nv_bfloat16* base = smem + (it & 1) * STAGE_;
        const __nv_bfloat16* sAh = base;
        const __nv_bfloat16* sAl = base + TILE_;
        const __nv_bfloat16* sBh = base + 2 * TILE_;
        const __nv_bfloat16* sBl = base + 3 * TILE_;

#pragma unroll
        for (int ks = 0; ks < 2; ks++) {
            uint32_t ah[2][4], al[2][4];
            {
                int arow_off = (lane & 15);
                int akc = ks * 16 + (lane >> 4) * 8;
#pragma unroll
                for (int mt = 0; mt < 2; mt++) {
                    int arow = wm * 32 + mt * 16 + arow_off;
                    ldsm_x4(ah[mt][0], ah[mt][1], ah[mt][2], ah[mt][3], sAh + arow * LDSM_ + akc);
                    ldsm_x4(al[mt][0], al[mt][1], al[mt][2], al[mt][3], sAl + arow * LDSM_ + akc);
                }
            }
            uint32_t bh[8][2], bl[8][2];
            {
                int nrow_off = (lane & 7) + ((lane >> 4) & 1) * 8;
                int bkc = ks * 16 + ((lane >> 3) & 1) * 8;
#pragma unroll
                for (int ntp = 0; ntp < 4; ntp++) {
                    int nrow = wn * 64 + ntp * 16 + nrow_off;
                    ldsm_x4(bh[2 * ntp][0], bh[2 * ntp][1], bh[2 * ntp + 1][0], bh[2 * ntp + 1][1],
                            sBh + nrow * LDSM_ + bkc);
                    ldsm_x4(bl[2 * ntp][0], bl[2 * ntp][1], bl[2 * ntp + 1][0], bl[2 * ntp + 1][1],
                            sBl + nrow * LDSM_ + bkc);
                }
            }
#pragma unroll
            for (int mt = 0; mt < 2; mt++)
#pragma unroll
                for (int nt = 0; nt < 8; nt++) {
                    mma_bf16(acc[mt][nt], ah[mt], bh[nt]);   // hi*hi
                    mma_bf16(acc[mt][nt], ah[mt], bl[nt]);   // hi*lo
                    mma_bf16(acc[mt][nt], al[mt], bh[nt]);   // lo*hi
                }
        }
        __syncthreads();
    }

    // ---------- epilogue ----------
#pragma unroll
    for (int mt = 0; mt < 2; mt++) {
        int row = bm + wm * 32 + mt * 16 + (lane >> 2);
#pragma unroll
        for (int nt = 0; nt < 8; nt++) {
            int col = bn + wn * 64 + nt * 8 + (lane & 3) * 2;
            if (col >= N) continue;
#pragma unroll
            for (int half = 0; half < 2; half++) {
                int r = row + half * 8;
                float2 st; st.x = acc[mt][nt][2 * half]; st.y = acc[mt][nt][2 * half + 1];
                *reinterpret_cast<float2*>(C + (size_t)r * ldc + col) = st;
            }
        }
    }
}

// ---------------- fp32-source bf16-split GEMM (round-2 version) for the small dt GEMM ---
// EPI==1: C = softplus(C + bias[col])
#define LDSM2_ (BK + 8)
template<int EPI>
__global__ __launch_bounds__(256)
void gemm_tc(const float* __restrict__ A, int lda,
             const float* __restrict__ Bw, int ldb,
             float* __restrict__ C, int ldc,
             int M, int N, int K,
             const float* __restrict__ bias)
{
    __shared__ __nv_bfloat16 sAh[128][LDSM2_];
    __shared__ __nv_bfloat16 sAl[128][LDSM2_];
    __shared__ __nv_bfloat16 sBh[128][LDSM2_];
    __shared__ __nv_bfloat16 sBl[128][LDSM2_];

    const int tid  = threadIdx.x;
    const int lane = tid & 31;
    const int wid  = tid >> 5;
    const int wm   = wid & 3;
    const int wn   = wid >> 2;

    const int bm = blockIdx.y * 128;
    const int bn = blockIdx.x * 128;

    const int lr = tid >> 3;
    const int lc = (tid & 7) * 4;

    float acc[2][8][4];
#pragma unroll
    for (int i = 0; i < 2; i++)
#pragma unroll
        for (int j = 0; j < 8; j++)
#pragma unroll
            for (int q = 0; q < 4; q++) acc[i][j][q] = 0.f;

    for (int k0 = 0; k0 < K; k0 += BK) {
#pragma unroll
        for (int p = 0; p < 4; p++) {
            int r = lr + p * 32;
            {
                float4 v = *reinterpret_cast<const float4*>(A + (size_t)(bm + r) * lda + k0 + lc);
                float f[4] = {v.x, v.y, v.z, v.w};
#pragma unroll
                for (int j = 0; j < 4; j++) {
                    __nv_bfloat16 h = __float2bfloat16(f[j]);
                    sAh[r][lc + j] = h;
                    sAl[r][lc + j] = __float2bfloat16(f[j] - __bfloat162float(h));
                }
            }
            {
                float4 v = make_float4(0.f, 0.f, 0.f, 0.f);
                int br = bn + r;
                if (br < N)
                    v = *reinterpret_cast<const float4*>(Bw + (size_t)br * ldb + k0 + lc);
                float f[4] = {v.x, v.y, v.z, v.w};
#pragma unroll
                for (int j = 0; j < 4; j++) {
                    __nv_bfloat16 h = __float2bfloat16(f[j]);
                    sBh[r][lc + j] = h;
                    sBl[r][lc + j] = __float2bfloat16(f[j] - __bfloat162float(h));
                }
            }
        }
        __syncthreads();

#pragma unroll
        for (int ks = 0; ks < 2; ks++) {
            uint32_t ah[2][4], al[2][4];
            {
                int arow_off = (lane & 15);
                int akc = ks * 16 + (lane >> 4) * 8;
#pragma unroll
                for (int mt = 0; mt < 2; mt++) {
                    int arow = wm * 32 + mt * 16 + arow_off;
                    ldsm_x4(ah[mt][0], ah[mt][1], ah[mt][2], ah[mt][3], &sAh[arow][akc]);
                    ldsm_x4(al[mt][0], al[mt][1], al[mt][2], al[mt][3], &sAl[arow][akc]);
                }
            }
            uint32_t bh[8][2], bl[8][2];
            {
                int nrow_off = (lane & 7) + ((lane >> 4) & 1) * 8;
                int bkc = ks * 16 + ((lane >> 3) & 1) * 8;
#pragma unroll
                for (int ntp = 0; ntp < 4; ntp++) {
                    int nrow = wn * 64 + ntp * 16 + nrow_off;
                    ldsm_x4(bh[2 * ntp][0], bh[2 * ntp][1], bh[2 * ntp + 1][0], bh[2 * ntp + 1][1],
                            &sBh[nrow][bkc]);
                    ldsm_x4(bl[2 * ntp][0], bl[2 * ntp][1], bl[2 * ntp + 1][0], bl[2 * ntp + 1][1],
                            &sBl[nrow][bkc]);
                }
            }
#pragma unroll
            for (int mt = 0; mt < 2; mt++)
#pragma unroll
                for (int nt = 0; nt < 8; nt++) {
                    mma_bf16(acc[mt][nt], ah[mt], bh[nt]);
                    mma_bf16(acc[mt][nt], ah[mt], bl[nt]);
                    mma_bf16(acc[mt][nt], al[mt], bh[nt]);
                }
        }
        __syncthreads();
    }

#pragma unroll
    for (int mt = 0; mt < 2; mt++) {
        int row = bm + wm * 32 + mt * 16 + (lane >> 2);
#pragma unroll
        for (int nt = 0; nt < 8; nt++) {
            int col = bn + wn * 64 + nt * 8 + (lane & 3) * 2;
            if (col >= N) continue;
#pragma unroll
            for (int half = 0; half < 2; half++) {
                int r = row + half * 8;
                float v0 = acc[mt][nt][2 * half + 0];
                float v1 = acc[mt][nt][2 * half + 1];
                if (EPI == 1) {
                    v0 += bias[col];
                    v1 += bias[col + 1];
                    v0 = (v0 > 20.f) ? v0 : log1pf(expf(v0));
                    v1 = (v1 > 20.f) ? v1 : log1pf(expf(v1));
                }
                float2 st; st.x = v0; st.y = v1;
                *reinterpret_cast<float2*>(C + (size_t)r * ldc + col) = st;
            }
        }
    }
}

// ---------------- depthwise conv (width 4, causal) + bias + silu; dual-format output ----
__global__ void conv_silu_kernel(const float* __restrict__ cw,
                                 const float* __restrict__ cb)
{
    int d = blockIdx.x * blockDim.x + threadIdx.x;
    int m = blockIdx.y;
    int l = m & (SEQ - 1);

    float acc = cb[d];
#pragma unroll
    for (int k = 0; k < 4; k++) {
        int ll = l - 3 + k;
        if (ll >= 0)
            acc = fmaf(cw[d * 4 + k], g_xz[(size_t)(m - 3 + k) * E2 + d], acc);
    }
    float s = acc / (1.f + expf(-acc));
    size_t o = (size_t)m * DI + d;
    g_x[o] = s;
    __nv_bfloat16 h = __float2bfloat16(s);
    g_xh[o] = h;
    g_xl[o] = __float2bfloat16(s - __bfloat162float(h));
}

// ---------------- selective scan: 4 threads/channel, 4 states each, shfl-reduce --------
__global__ void scan_kernel(const float* __restrict__ A_log,
                            const float* __restrict__ Dp)
{
    int t = blockIdx.x * blockDim.x + threadIdx.x;   // 0..16383
    int chan = t >> 2;
    int sub  = t & 3;
    int b = chan >> 11;
    int d = chan & (DI - 1);

    float Arow[4];
#pragma unroll
    for (int j = 0; j < 4; j++) Arow[j] = -expf(A_log[d * DS + sub * 4 + j]);
    float Dd = Dp[d];

    float h0 = 0.f, h1 = 0.f, h2 = 0.f, h3 = 0.f;
    size_t mb = (size_t)b * SEQ;

    // preload step 0
    size_t m0 = mb;
    float dt = g_delta[m0 * DI + d];
    float xv = g_x[m0 * DI + d];
    float zv = g_xz[m0 * E2 + DI + d];
    float4 Bv = *reinterpret_cast<const float4*>(g_xdbl + m0 * XDBL_W + DTR + sub * 4);
    float4 Cv = *reinterpret_cast<const float4*>(g_xdbl + m0 * XDBL_W + DTR + DS + sub * 4);

    for (int l = 0; l < SEQ; l++) {
        float dtn = 0.f, xvn = 0.f, zvn = 0.f;
        float4 Bn = make_float4(0.f, 0.f, 0.f, 0.f), Cn = Bn;
        if (l + 1 < SEQ) {
            size_t m2 = mb + l + 1;
            dtn = g_delta[m2 * DI + d];
            xvn = g_x[m2 * DI + d];
            zvn = g_xz[m2 * E2 + DI + d];
            Bn = *reinterpret_cast<const float4*>(g_xdbl + m2 * XDBL_W + DTR + sub * 4);
            Cn = *reinterpret_cast<const float4*>(g_xdbl + m2 * XDBL_W + DTR + DS + sub * 4);
        }

        float dx = dt * xv;
        float e0 = __expf(dt * Arow[0]);
        float e1 = __expf(dt * Arow[1]);
        float e2 = __expf(dt * Arow[2]);
        float e3 = __expf(dt * Arow[3]);
        h0 = fmaf(e0, h0, dx * Bv.x);
        h1 = fmaf(e1, h1, dx * Bv.y);
        h2 = fmaf(e2, h2, dx * Bv.z);
        h3 = fmaf(e3, h3, dx * Bv.w);
        float part = h0 * Cv.x + h1 * Cv.y + h2 * Cv.z + h3 * Cv.w;
        part += __shfl_xor_sync(0xFFFFFFFFu, part, 1);
        part += __shfl_xor_sync(0xFFFFFFFFu, part, 2);

        if (sub == 0) {
            float sz = zv / (1.f + __expf(-zv));
            float yv = (part + Dd * xv) * sz;
            size_t o = (mb + l) * DI + d;
            __nv_bfloat16 hh = __float2bfloat16(yv);
            g_yh[o] = hh;
            g_yl[o] = __float2bfloat16(yv - __bfloat162float(hh));
        }

        dt = dtn; xv = xvn; zv = zvn; Bv = Bn; Cv = Cn;
    }
}

// ---------------- launch ----------------
extern "C" void kernel_launch(void* const* d_in, const int* in_sizes, int n_in,
                              void* d_out, int out_size)
{
    const float* hs        = (const float*)d_in[0];
    const float* in_proj_w = (const float*)d_in[1];
    const float* conv_w    = (const float*)d_in[2];
    const float* conv_b    = (const float*)d_in[3];
    const float* x_proj_w  = (const float*)d_in[4];
    const float* dt_proj_w = (const float*)d_in[5];
    const float* dt_proj_b = (const float*)d_in[6];
    const float* A_log     = (const float*)d_in[7];
    const float* Dp        = (const float*)d_in[8];
    const float* out_w     = (const float*)d_in[9];
    float* out = (float*)d_out;

    float *p_xz, *p_x, *p_xdbl, *p_delta;
    cudaGetSymbolAddress((void**)&p_xz,    g_xz);
    cudaGetSymbolAddress((void**)&p_x,     g_x);
    cudaGetSymbolAddress((void**)&p_xdbl,  g_xdbl);
    cudaGetSymbolAddress((void**)&p_delta, g_delta);

    __nv_bfloat16 *p_hs_h, *p_hs_l, *p_w1_h, *p_w1_l, *p_xp_h, *p_xp_l, *p_ow_h, *p_ow_l;
    __nv_bfloat16 *p_xh, *p_xl, *p_yh, *p_yl;
    cudaGetSymbolAddress((void**)&p_hs_h, g_hs_h);
    cudaGetSymbolAddress((void**)&p_hs_l, g_hs_l);
    cudaGetSymbolAddress((void**)&p_w1_h, g_w1_h);
    cudaGetSymbolAddress((void**)&p_w1_l, g_w1_l);
    cudaGetSymbolAddress((void**)&p_xp_h, g_xp_h);
    cudaGetSymbolAddress((void**)&p_xp_l, g_xp_l);
    cudaGetSymbolAddress((void**)&p_ow_h, g_ow_h);
    cudaGetSymbolAddress((void**)&p_ow_l, g_ow_l);
    cudaGetSymbolAddress((void**)&p_xh, g_xh);
    cudaGetSymbolAddress((void**)&p_xl, g_xl);
    cudaGetSymbolAddress((void**)&p_yh, g_yh);
    cudaGetSymbolAddress((void**)&p_yl, g_yl);

    static const int SMEM_BYTES = 2 * STAGE_ * (int)sizeof(__nv_bfloat16);   // 81920
    cudaFuncSetAttribute(gemm_bf, cudaFuncAttributeMaxDynamicSharedMemorySize, SMEM_BYTES);

    // C0: input conversions (fp32 -> bf16 hi/lo)
    {
        int n;
        n = MROWS * DM;
        cvt_kernel<<<n / 4 / 256, 256>>>(hs, p_hs_h, p_hs_l, n, n);
        n = E2 * DM;
        cvt_kernel<<<n / 4 / 256, 256>>>(in_proj_w, p_w1_h, p_w1_l, n, n);
        cvt_kernel<<<128 * DI / 4 / 256, 256>>>(x_proj_w, p_xp_h, p_xp_l, 96 * DI, 128 * DI);
        n = DM * DI;
        cvt_kernel<<<n / 4 / 256, 256>>>(out_w, p_ow_h, p_ow_l, n, n);
    }

    // K1: xz = hs . in_proj_w^T   (4096 x 4096 x 1024)
    gemm_bf<<<dim3(E2 / 128, MROWS / 128), 256, SMEM_BYTES>>>(
        p_hs_h, p_hs_l, DM, p_w1_h, p_w1_l, DM, p_xz, E2, MROWS, E2, DM);

    // K2: depthwise conv + bias + silu (fp32 + bf16 hi/lo out)
    conv_silu_kernel<<<dim3(DI / 256, MROWS), 256>>>(conv_w, conv_b);

    // K3: x_dbl = x . x_proj_w^T  (4096 x 96 x 2048), B padded to 128 rows
    gemm_bf<<<dim3(1, MROWS / 128), 256, SMEM_BYTES>>>(
        p_xh, p_xl, DI, p_xp_h, p_xp_l, DI, p_xdbl, XDBL_W, MROWS, XDBL_W, DI);

    // K4: delta = softplus(x_dbl[:, :64] . dt_proj_w^T + b)   (4096 x 2048 x 64)
    gemm_tc<1><<<dim3(DI / 128, MROWS / 128), 256>>>(
        p_xdbl, XDBL_W, dt_proj_w, DTR, p_delta, DI, MROWS, DI, DTR, dt_proj_b);

    // K5: selective scan + gating (bf16 hi/lo y out)
    scan_kernel<<<64, 256>>>(A_log, Dp);

    // K6: out = y . out_w^T       (4096 x 1024 x 2048)
    gemm_bf<<<dim3(DM / 128, MROWS / 128), 256, SMEM_BYTES>>>(
        p_yh, p_yl, DI, p_ow_h, p_ow_l, DI, out, DM, MROWS, DM, DI);
}

// round 4
// speedup vs baseline: 2.2828x; 1.0118x over previous
#include <cuda_runtime.h>
#include <cuda_bf16.h>
#include <math.h>
#include <stdint.h>

// ---------------- problem constants ----------------
#define B_SZ   2
#define SEQ    2048
#define DM     1024
#define DI     2048
#define DS     16
#define DTR    64
#define MROWS  (B_SZ * SEQ)      // 4096
#define E2     (2 * DI)          // 4096
#define XDBL_W 96
#define KSPL   8                 // split-K factor for K3

// ---------------- scratch (device globals) ----------------
static __device__ float g_xz   [(size_t)MROWS * E2];
static __device__ float g_x    [(size_t)MROWS * DI];
static __device__ float g_xdbl [(size_t)MROWS * XDBL_W];
static __device__ float g_delta[(size_t)MROWS * DI];
static __device__ float g_part [(size_t)KSPL * MROWS * XDBL_W];   // K3 split-K partials

static __device__ __nv_bfloat16 g_hs_h[(size_t)MROWS * DM];
static __device__ __nv_bfloat16 g_hs_l[(size_t)MROWS * DM];
static __device__ __nv_bfloat16 g_w1_h[(size_t)E2 * DM];
static __device__ __nv_bfloat16 g_w1_l[(size_t)E2 * DM];
static __device__ __nv_bfloat16 g_xp_h[(size_t)128 * DI];   // x_proj padded 96->128 rows
static __device__ __nv_bfloat16 g_xp_l[(size_t)128 * DI];
static __device__ __nv_bfloat16 g_dw_h[(size_t)DI * DTR];   // dt_proj_w
static __device__ __nv_bfloat16 g_dw_l[(size_t)DI * DTR];
static __device__ __nv_bfloat16 g_ow_h[(size_t)DM * DI];
static __device__ __nv_bfloat16 g_ow_l[(size_t)DM * DI];
static __device__ __nv_bfloat16 g_xh  [(size_t)MROWS * DI];
static __device__ __nv_bfloat16 g_xl  [(size_t)MROWS * DI];
static __device__ __nv_bfloat16 g_xdh [(size_t)MROWS * XDBL_W];  // x_dbl bf16 hi/lo
static __device__ __nv_bfloat16 g_xdl [(size_t)MROWS * XDBL_W];
static __device__ __nv_bfloat16 g_yh  [(size_t)MROWS * DI];
static __device__ __nv_bfloat16 g_yl  [(size_t)MROWS * DI];

// ---------------- tensor-core helpers ----------------
__device__ __forceinline__ void ldsm_x4(uint32_t& r0, uint32_t& r1, uint32_t& r2, uint32_t& r3,
                                        const __nv_bfloat16* p)
{
    uint32_t addr = (uint32_t)__cvta_generic_to_shared(p);
    asm volatile("ldmatrix.sync.aligned.m8n8.x4.shared.b16 {%0,%1,%2,%3}, [%4];\n"
                 : "=r"(r0), "=r"(r1), "=r"(r2), "=r"(r3) : "r"(addr));
}

__device__ __forceinline__ void mma_bf16(float* c, const uint32_t* a, const uint32_t* b)
{
    asm volatile(
        "mma.sync.aligned.m16n8k16.row.col.f32.bf16.bf16.f32 "
        "{%0,%1,%2,%3}, {%4,%5,%6,%7}, {%8,%9}, {%0,%1,%2,%3};\n"
        : "+f"(c[0]), "+f"(c[1]), "+f"(c[2]), "+f"(c[3])
        : "r"(a[0]), "r"(a[1]), "r"(a[2]), "r"(a[3]), "r"(b[0]), "r"(b[1]));
}

__device__ __forceinline__ void cp16(__nv_bfloat16* dst, const __nv_bfloat16* src)
{
    uint32_t d = (uint32_t)__cvta_generic_to_shared(dst);
    asm volatile("cp.async.cg.shared.global [%0], [%1], 16;\n" :: "r"(d), "l"(src));
}
__device__ __forceinline__ void cp_commit() { asm volatile("cp.async.commit_group;\n"); }
template<int N>
__device__ __forceinline__ void cp_wait()   { asm volatile("cp.async.wait_group %0;\n" :: "n"(N)); }

// ---------------- fp32 -> bf16 hi/lo split ----------------
__global__ void cvt_kernel(const float* __restrict__ src,
                           __nv_bfloat16* __restrict__ hi,
                           __nv_bfloat16* __restrict__ lo,
                           int n_valid, int n_total)
{
    int i4 = (blockIdx.x * blockDim.x + threadIdx.x) * 4;
    if (i4 >= n_total) return;
    float4 v = make_float4(0.f, 0.f, 0.f, 0.f);
    if (i4 < n_valid) v = *reinterpret_cast<const float4*>(src + i4);
    __nv_bfloat16 h[4], l[4];
    float f[4] = {v.x, v.y, v.z, v.w};
#pragma unroll
    for (int j = 0; j < 4; j++) {
        h[j] = __float2bfloat16(f[j]);
        l[j] = __float2bfloat16(f[j] - __bfloat162float(h[j]));
    }
    *reinterpret_cast<uint2*>(hi + i4) = *reinterpret_cast<uint2*>(h);
    *reinterpret_cast<uint2*>(lo + i4) = *reinterpret_cast<uint2*>(l);
}

// ---------------- bf16-split HMMA GEMM, 3-stage cp.async, frag double-buffer -----------
// C[M,N] = A[M,K] * B[N,K]^T; 128x128x32 tile, 8 warps, warp 32x64.
// blockIdx.z: split-K chunk (A,B advanced by z*kzo elems; C by z*czs elems).
// EPI==1: C = softplus(C + bias[col])
#define BK    32
#define LDSM_ 40
#define TILE_ (128 * LDSM_)
#define STAGE_ (4 * TILE_)
#define NSTG  3

template<int EPI>
__global__ __launch_bounds__(256)
void gemm_bf(const __nv_bfloat16* __restrict__ Ah, const __nv_bfloat16* __restrict__ Al, int lda,
             const __nv_bfloat16* __restrict__ Bh, const __nv_bfloat16* __restrict__ Bl, int ldb,
             float* __restrict__ C, int ldc,
             int M, int N, int K,
             int kzo, size_t czs,
             const float* __restrict__ bias)
{
    extern __shared__ __nv_bfloat16 smem[];

    const int tid  = threadIdx.x;
    const int lane = tid & 31;
    const int wid  = tid >> 5;
    const int wm   = wid & 3;
    const int wn   = wid >> 2;

    const int bm = blockIdx.y * 128;
    const int bn = blockIdx.x * 128;

    Ah += (size_t)blockIdx.z * kzo;
    Al += (size_t)blockIdx.z * kzo;
    Bh += (size_t)blockIdx.z * kzo;
    Bl += (size_t)blockIdx.z * kzo;
    C  += (size_t)blockIdx.z * czs;

    const int lr = tid >> 2;
    const int lc = (tid & 3) * 8;

    const __nv_bfloat16* srcA_h = Ah + (size_t)(bm + lr) * lda + lc;
    const __nv_bfloat16* srcA_l = Al + (size_t)(bm + lr) * lda + lc;
    const __nv_bfloat16* srcB_h = Bh + (size_t)(bn + lr) * ldb + lc;
    const __nv_bfloat16* srcB_l = Bl + (size_t)(bn + lr) * ldb + lc;

    float acc[2][8][4];
#pragma unroll
    for (int i = 0; i < 2; i++)
#pragma unroll
        for (int j = 0; j < 8; j++)
#pragma unroll
            for (int q = 0; q < 4; q++) acc[i][j][q] = 0.f;

    const int KT = K / BK;

    auto load_stage = [&](int s, int k0) {
        __nv_bfloat16* base = smem + s * STAGE_;
#pragma unroll
        for (int p = 0; p < 2; p++) {
            int r = lr + p * 64;
            size_t soA = (size_t)p * 64 * lda + k0;
            size_t soB = (size_t)p * 64 * ldb + k0;
            cp16(base + r * LDSM_ + lc,              srcA_h + soA);
            cp16(base + TILE_ + r * LDSM_ + lc,      srcA_l + soA);
            cp16(base + 2 * TILE_ + r * LDSM_ + lc,  srcB_h + soB);
            cp16(base + 3 * TILE_ + r * LDSM_ + lc,  srcB_l + soB);
        }
    };

    load_stage(0, 0);
    cp_commit();
    if (KT > 1) load_stage(1, BK);
    cp_commit();

    for (int it = 0; it < KT; it++) {
        if (it + 2 < KT) load_stage((it + 2) % NSTG, (it + 2) * BK);
        cp_commit();
        cp_wait<2>();
        __syncthreads();

        const __nv_bfloat16* base = smem + (it % NSTG) * STAGE_;
        const __nv_bfloat16* sAh = base;
        const __nv_bfloat16* sAl = base + TILE_;
        const __nv_bfloat16* sBh = base + 2 * TILE_;
        const __nv_bfloat16* sBl = base + 3 * TILE_;

        uint32_t ah[2][2][4], al[2][2][4], bh[2][8][2], bl[2][8][2];

        auto ldf = [&](int q, int ks) {
            int arow_off = lane & 15;
            int akc = ks * 16 + (lane >> 4) * 8;
#pragma unroll
            for (int mt = 0; mt < 2; mt++) {
                int arow = wm * 32 + mt * 16 + arow_off;
                ldsm_x4(ah[q][mt][0], ah[q][mt][1], ah[q][mt][2], ah[q][mt][3],
                        sAh + arow * LDSM_ + akc);
                ldsm_x4(al[q][mt][0], al[q][mt][1], al[q][mt][2], al[q][mt][3],
                        sAl + arow * LDSM_ + akc);
            }
            int nrow_off = (lane & 7) + ((lane >> 4) & 1) * 8;
            int bkc = ks * 16 + ((lane >> 3) & 1) * 8;
#pragma unroll
            for (int ntp = 0; ntp < 4; ntp++) {
                int nrow = wn * 64 + ntp * 16 + nrow_off;
                ldsm_x4(bh[q][2 * ntp][0], bh[q][2 * ntp][1],
                        bh[q][2 * ntp + 1][0], bh[q][2 * ntp + 1][1],
                        sBh + nrow * LDSM_ + bkc);
                ldsm_x4(bl[q][2 * ntp][0], bl[q][2 * ntp][1],
                        bl[q][2 * ntp + 1][0], bl[q][2 * ntp + 1][1],
                        sBl + nrow * LDSM_ + bkc);
            }
        };

        ldf(0, 0);
#pragma unroll
        for (int ks = 0; ks < 2; ks++) {
            if (ks == 0) ldf(1, 1);     // prefetch next k16 while ks=0 MMAs issue
#pragma unroll
            for (int mt = 0; mt < 2; mt++)
#pragma unroll
                for (int nt = 0; nt < 8; nt++) {
                    mma_bf16(acc[mt][nt], ah[ks][mt], bh[ks][nt]);
                    mma_bf16(acc[mt][nt], ah[ks][mt], bl[ks][nt]);
                    mma_bf16(acc[mt][nt], al[ks][mt], bh[ks][nt]);
                }
        }
        __syncthreads();
    }

    // ---------- epilogue ----------
#pragma unroll
    for (int mt = 0; mt < 2; mt++) {
        int row = bm + wm * 32 + mt * 16 + (lane >> 2);
#pragma unroll
        for (int nt = 0; nt < 8; nt++) {
            int col = bn + wn * 64 + nt * 8 + (lane & 3) * 2;
            if (col >= N) continue;
#pragma unroll
            for (int half = 0; half < 2; half++) {
                int r = row + half * 8;
                float v0 = acc[mt][nt][2 * half + 0];
                float v1 = acc[mt][nt][2 * half + 1];
                if (EPI == 1) {
                    v0 += bias[col];
                    v1 += bias[col + 1];
                    v0 = (v0 > 20.f) ? v0 : log1pf(expf(v0));
                    v1 = (v1 > 20.f) ? v1 : log1pf(expf(v1));
                }
                float2 st; st.x = v0; st.y = v1;
                *reinterpret_cast<float2*>(C + (size_t)r * ldc + col) = st;
            }
        }
    }
}

// ---------------- K3 split-K reduce: sum partials, emit fp32 + bf16 hi/lo --------------
__global__ void k3_reduce_kernel()
{
    int i = blockIdx.x * blockDim.x + threadIdx.x;   // 0 .. MROWS*96-1
    float s = 0.f;
#pragma unroll
    for (int z = 0; z < KSPL; z++)
        s += g_part[(size_t)z * MROWS * XDBL_W + i];
    g_xdbl[i] = s;
    __nv_bfloat16 h = __float2bfloat16(s);
    g_xdh[i] = h;
    g_xdl[i] = __float2bfloat16(s - __bfloat162float(h));
}

// ---------------- depthwise conv + bias + silu; dual-format output ----------------
__global__ void conv_silu_kernel(const float* __restrict__ cw,
                                 const float* __restrict__ cb)
{
    int d = blockIdx.x * blockDim.x + threadIdx.x;
    int m = blockIdx.y;
    int l = m & (SEQ - 1);

    float acc = cb[d];
#pragma unroll
    for (int k = 0; k < 4; k++) {
        int ll = l - 3 + k;
        if (ll >= 0)
            acc = fmaf(cw[d * 4 + k], g_xz[(size_t)(m - 3 + k) * E2 + d], acc);
    }
    float s = acc / (1.f + expf(-acc));
    size_t o = (size_t)m * DI + d;
    g_x[o] = s;
    __nv_bfloat16 h = __float2bfloat16(s);
    g_xh[o] = h;
    g_xl[o] = __float2bfloat16(s - __bfloat162float(h));
}

// ---------------- selective scan: 8 threads/channel, 2 states each ---------------------
__global__ void scan_kernel(const float* __restrict__ A_log,
                            const float* __restrict__ Dp)
{
    int t = blockIdx.x * blockDim.x + threadIdx.x;   // 0..32767
    int chan = t >> 3;
    int sub  = t & 7;
    int b = chan >> 11;
    int d = chan & (DI - 1);

    float A0 = -expf(A_log[d * DS + sub * 2 + 0]);
    float A1 = -expf(A_log[d * DS + sub * 2 + 1]);
    float Dd = Dp[d];

    float h0 = 0.f, h1 = 0.f;
    size_t mb = (size_t)b * SEQ;

    // preload step 0
    float dt = g_delta[mb * DI + d];
    float xv = g_x[mb * DI + d];
    float zv = g_xz[mb * E2 + DI + d];
    float2 Bv = *reinterpret_cast<const float2*>(g_xdbl + mb * XDBL_W + DTR + sub * 2);
    float2 Cv = *reinterpret_cast<const float2*>(g_xdbl + mb * XDBL_W + DTR + DS + sub * 2);

    for (int l = 0; l < SEQ; l++) {
        float dtn = 0.f, xvn = 0.f, zvn = 0.f;
        float2 Bn = make_float2(0.f, 0.f), Cn = Bn;
        if (l + 1 < SEQ) {
            size_t m2 = mb + l + 1;
            dtn = g_delta[m2 * DI + d];
            xvn = g_x[m2 * DI + d];
            zvn = g_xz[m2 * E2 + DI + d];
            Bn = *reinterpret_cast<const float2*>(g_xdbl + m2 * XDBL_W + DTR + sub * 2);
            Cn = *reinterpret_cast<const float2*>(g_xdbl + m2 * XDBL_W + DTR + DS + sub * 2);
        }

        float dx = dt * xv;
        float e0 = __expf(dt * A0);
        float e1 = __expf(dt * A1);
        h0 = fmaf(e0, h0, dx * Bv.x);
        h1 = fmaf(e1, h1, dx * Bv.y);
        float part = fmaf(h1, Cv.y, h0 * Cv.x);
        part += __shfl_xor_sync(0xFFFFFFFFu, part, 1);
        part += __shfl_xor_sync(0xFFFFFFFFu, part, 2);
        part += __shfl_xor_sync(0xFFFFFFFFu, part, 4);

        if (sub == 0) {
            float sz = zv / (1.f + __expf(-zv));
            float yv = (part + Dd * xv) * sz;
            size_t o = (mb + l) * DI + d;
            __nv_bfloat16 hh = __float2bfloat16(yv);
            g_yh[o] = hh;
            g_yl[o] = __float2bfloat16(yv - __bfloat162float(hh));
        }

        dt = dtn; xv = xvn; zv = zvn; Bv = Bn; Cv = Cn;
    }
}

// ---------------- launch ----------------
extern "C" void kernel_launch(void* const* d_in, const int* in_sizes, int n_in,
                              void* d_out, int out_size)
{
    const float* hs        = (const float*)d_in[0];
    const float* in_proj_w = (const float*)d_in[1];
    const float* conv_w    = (const float*)d_in[2];
    const float* conv_b    = (const float*)d_in[3];
    const float* x_proj_w  = (const float*)d_in[4];
    const float* dt_proj_w = (const float*)d_in[5];
    const float* dt_proj_b = (const float*)d_in[6];
    const float* A_log     = (const float*)d_in[7];
    const float* Dp        = (const float*)d_in[8];
    const float* out_w     = (const float*)d_in[9];
    float* out = (float*)d_out;

    float *p_xz, *p_xdbl, *p_delta, *p_part;
    cudaGetSymbolAddress((void**)&p_xz,    g_xz);
    cudaGetSymbolAddress((void**)&p_xdbl,  g_xdbl);
    cudaGetSymbolAddress((void**)&p_delta, g_delta);
    cudaGetSymbolAddress((void**)&p_part,  g_part);

    __nv_bfloat16 *p_hs_h, *p_hs_l, *p_w1_h, *p_w1_l, *p_xp_h, *p_xp_l;
    __nv_bfloat16 *p_dw_h, *p_dw_l, *p_ow_h, *p_ow_l;
    __nv_bfloat16 *p_xh, *p_xl, *p_xdh, *p_xdl, *p_yh, *p_yl;
    cudaGetSymbolAddress((void**)&p_hs_h, g_hs_h);
    cudaGetSymbolAddress((void**)&p_hs_l, g_hs_l);
    cudaGetSymbolAddress((void**)&p_w1_h, g_w1_h);
    cudaGetSymbolAddress((void**)&p_w1_l, g_w1_l);
    cudaGetSymbolAddress((void**)&p_xp_h, g_xp_h);
    cudaGetSymbolAddress((void**)&p_xp_l, g_xp_l);
    cudaGetSymbolAddress((void**)&p_dw_h, g_dw_h);
    cudaGetSymbolAddress((void**)&p_dw_l, g_dw_l);
    cudaGetSymbolAddress((void**)&p_ow_h, g_ow_h);
    cudaGetSymbolAddress((void**)&p_ow_l, g_ow_l);
    cudaGetSymbolAddress((void**)&p_xh, g_xh);
    cudaGetSymbolAddress((void**)&p_xl, g_xl);
    cudaGetSymbolAddress((void**)&p_xdh, g_xdh);
    cudaGetSymbolAddress((void**)&p_xdl, g_xdl);
    cudaGetSymbolAddress((void**)&p_yh, g_yh);
    cudaGetSymbolAddress((void**)&p_yl, g_yl);

    static const int SMEM_BYTES = NSTG * STAGE_ * (int)sizeof(__nv_bfloat16);   // 122880
    cudaFuncSetAttribute(gemm_bf<0>, cudaFuncAttributeMaxDynamicSharedMemorySize, SMEM_BYTES);
    cudaFuncSetAttribute(gemm_bf<1>, cudaFuncAttributeMaxDynamicSharedMemorySize, SMEM_BYTES);

    // C0: conversions (fp32 -> bf16 hi/lo)
    {
        int n;
        n = MROWS * DM;
        cvt_kernel<<<n / 4 / 256, 256>>>(hs, p_hs_h, p_hs_l, n, n);
        n = E2 * DM;
        cvt_kernel<<<n / 4 / 256, 256>>>(in_proj_w, p_w1_h, p_w1_l, n, n);
        cvt_kernel<<<128 * DI / 4 / 256, 256>>>(x_proj_w, p_xp_h, p_xp_l, 96 * DI, 128 * DI);
        n = DI * DTR;
        cvt_kernel<<<n / 4 / 256, 256>>>(dt_proj_w, p_dw_h, p_dw_l, n, n);
        n = DM * DI;
        cvt_kernel<<<n / 4 / 256, 256>>>(out_w, p_ow_h, p_ow_l, n, n);
    }

    // K1: xz = hs . in_proj_w^T   (4096 x 4096 x 1024)
    gemm_bf<0><<<dim3(E2 / 128, MROWS / 128, 1), 256, SMEM_BYTES>>>(
        p_hs_h, p_hs_l, DM, p_w1_h, p_w1_l, DM, p_xz, E2, MROWS, E2, DM, 0, 0, nullptr);

    // K2: depthwise conv + bias + silu
    conv_silu_kernel<<<dim3(DI / 256, MROWS), 256>>>(conv_w, conv_b);

    // K3: x_dbl partials = x . x_proj_w^T  (4096 x 96 x 2048), split-K x8
    gemm_bf<0><<<dim3(1, MROWS / 128, KSPL), 256, SMEM_BYTES>>>(
        p_xh, p_xl, DI, p_xp_h, p_xp_l, DI, p_part, XDBL_W, MROWS, XDBL_W, DI / KSPL,
        DI / KSPL, (size_t)MROWS * XDBL_W, nullptr);
    k3_reduce_kernel<<<MROWS * XDBL_W / 256, 256>>>();

    // K4: delta = softplus(x_dbl[:, :64] . dt_proj_w^T + b)   (4096 x 2048 x 64)
    gemm_bf<1><<<dim3(DI / 128, MROWS / 128, 1), 256, SMEM_BYTES>>>(
        p_xdh, p_xdl, XDBL_W, p_dw_h, p_dw_l, DTR, p_delta, DI, MROWS, DI, DTR,
        0, 0, dt_proj_b);

    // K5: selective scan + gating
    scan_kernel<<<128, 256>>>(A_log, Dp);

    // K6: out = y . out_w^T       (4096 x 1024 x 2048)
    gemm_bf<0><<<dim3(DM / 128, MROWS / 128, 1), 256, SMEM_BYTES>>>(
        p_yh, p_yl, DI, p_ow_h, p_ow_l, DI, out, DM, MROWS, DM, DI, 0, 0, nullptr);
}

// round 6
// speedup vs baseline: 2.3885x; 1.0463x over previous
#include <cuda_runtime.h>
#include <cuda_bf16.h>
#include <math.h>
#include <stdint.h>

// ---------------- problem constants ----------------
#define B_SZ   2
#define SEQ    2048
#define DM     1024
#define DI     2048
#define DS     16
#define DTR    64
#define MROWS  (B_SZ * SEQ)      // 4096
#define E2     (2 * DI)          // 4096
#define XDBL_W 96
#define KSPL   8                 // split-K factor for K3

// ---------------- scratch (device globals) ----------------
static __device__ float g_xz   [(size_t)MROWS * E2];
static __device__ float g_x    [(size_t)MROWS * DI];
static __device__ float g_xdbl [(size_t)MROWS * XDBL_W];
static __device__ float g_delta[(size_t)MROWS * DI];
static __device__ float g_part [(size_t)KSPL * MROWS * XDBL_W];

static __device__ __nv_bfloat16 g_hs_h[(size_t)MROWS * DM];
static __device__ __nv_bfloat16 g_hs_l[(size_t)MROWS * DM];
static __device__ __nv_bfloat16 g_w1_h[(size_t)E2 * DM];
static __device__ __nv_bfloat16 g_w1_l[(size_t)E2 * DM];
static __device__ __nv_bfloat16 g_xp_h[(size_t)128 * DI];
static __device__ __nv_bfloat16 g_xp_l[(size_t)128 * DI];
static __device__ __nv_bfloat16 g_dw_h[(size_t)DI * DTR];
static __device__ __nv_bfloat16 g_dw_l[(size_t)DI * DTR];
static __device__ __nv_bfloat16 g_ow_h[(size_t)DM * DI];
static __device__ __nv_bfloat16 g_ow_l[(size_t)DM * DI];
static __device__ __nv_bfloat16 g_xh  [(size_t)MROWS * DI];
static __device__ __nv_bfloat16 g_xl  [(size_t)MROWS * DI];
static __device__ __nv_bfloat16 g_xdh [(size_t)MROWS * XDBL_W];
static __device__ __nv_bfloat16 g_xdl [(size_t)MROWS * XDBL_W];
static __device__ __nv_bfloat16 g_yh  [(size_t)MROWS * DI];
static __device__ __nv_bfloat16 g_yl  [(size_t)MROWS * DI];

// ---------------- tensor-core helpers ----------------
__device__ __forceinline__ void ldsm_x4(uint32_t& r0, uint32_t& r1, uint32_t& r2, uint32_t& r3,
                                        const __nv_bfloat16* p)
{
    uint32_t addr = (uint32_t)__cvta_generic_to_shared(p);
    asm volatile("ldmatrix.sync.aligned.m8n8.x4.shared.b16 {%0,%1,%2,%3}, [%4];\n"
                 : "=r"(r0), "=r"(r1), "=r"(r2), "=r"(r3) : "r"(addr));
}

__device__ __forceinline__ void mma_bf16(float* c, const uint32_t* a, const uint32_t* b)
{
    asm volatile(
        "mma.sync.aligned.m16n8k16.row.col.f32.bf16.bf16.f32 "
        "{%0,%1,%2,%3}, {%4,%5,%6,%7}, {%8,%9}, {%0,%1,%2,%3};\n"
        : "+f"(c[0]), "+f"(c[1]), "+f"(c[2]), "+f"(c[3])
        : "r"(a[0]), "r"(a[1]), "r"(a[2]), "r"(a[3]), "r"(b[0]), "r"(b[1]));
}

__device__ __forceinline__ void cp16(__nv_bfloat16* dst, const __nv_bfloat16* src)
{
    uint32_t d = (uint32_t)__cvta_generic_to_shared(dst);
    asm volatile("cp.async.cg.shared.global [%0], [%1], 16;\n" :: "r"(d), "l"(src));
}
__device__ __forceinline__ void cp_commit() { asm volatile("cp.async.commit_group;\n"); }
template<int N>
__device__ __forceinline__ void cp_wait()   { asm volatile("cp.async.wait_group %0;\n" :: "n"(N)); }

// ---------------- fp32 -> bf16 hi/lo split ----------------
__global__ void cvt_kernel(const float* __restrict__ src,
                           __nv_bfloat16* __restrict__ hi,
                           __nv_bfloat16* __restrict__ lo,
                           int n_valid, int n_total)
{
    int i4 = (blockIdx.x * blockDim.x + threadIdx.x) * 4;
    if (i4 >= n_total) return;
    float4 v = make_float4(0.f, 0.f, 0.f, 0.f);
    if (i4 < n_valid) v = *reinterpret_cast<const float4*>(src + i4);
    __nv_bfloat16 h[4], l[4];
    float f[4] = {v.x, v.y, v.z, v.w};
#pragma unroll
    for (int j = 0; j < 4; j++) {
        h[j] = __float2bfloat16(f[j]);
        l[j] = __float2bfloat16(f[j] - __bfloat162float(h[j]));
    }
    *reinterpret_cast<uint2*>(hi + i4) = *reinterpret_cast<uint2*>(h);
    *reinterpret_cast<uint2*>(lo + i4) = *reinterpret_cast<uint2*>(l);
}

// ---------------- bf16-split HMMA GEMM, 2-stage cp.async (2 CTAs/SM), frag dbl-buffer --
// C[M,N] = A[M,K] * B[N,K]^T; 128x128x32 tile, 8 warps, warp 32x64.
// blockIdx.z: split-K chunk (A,B advanced by z*kzo elems; C by z*czs elems).
// EPI==1: C = softplus(C + bias[col])
#define BK    32
#define LDSM_ 40
#define TILE_ (128 * LDSM_)
#define STAGE_ (4 * TILE_)
#define SMEM_BYTES (2 * STAGE_ * (int)sizeof(__nv_bfloat16))   // 81920

template<int EPI>
__global__ __launch_bounds__(256, 2)
void gemm_bf(const __nv_bfloat16* __restrict__ Ah, const __nv_bfloat16* __restrict__ Al, int lda,
             const __nv_bfloat16* __restrict__ Bh, const __nv_bfloat16* __restrict__ Bl, int ldb,
             float* __restrict__ C, int ldc,
             int M, int N, int K,
             int kzo, size_t czs,
             const float* __restrict__ bias)
{
    extern __shared__ __nv_bfloat16 smem[];

    const int tid  = threadIdx.x;
    const int lane = tid & 31;
    const int wid  = tid >> 5;
    const int wm   = wid & 3;
    const int wn   = wid >> 2;

    const int bm = blockIdx.y * 128;
    const int bn = blockIdx.x * 128;

    Ah += (size_t)blockIdx.z * kzo;
    Al += (size_t)blockIdx.z * kzo;
    Bh += (size_t)blockIdx.z * kzo;
    Bl += (size_t)blockIdx.z * kzo;
    C  += (size_t)blockIdx.z * czs;

    const int lr = tid >> 2;
    const int lc = (tid & 3) * 8;

    const __nv_bfloat16* srcA_h = Ah + (size_t)(bm + lr) * lda + lc;
    const __nv_bfloat16* srcA_l = Al + (size_t)(bm + lr) * lda + lc;
    const __nv_bfloat16* srcB_h = Bh + (size_t)(bn + lr) * ldb + lc;
    const __nv_bfloat16* srcB_l = Bl + (size_t)(bn + lr) * ldb + lc;

    float acc[2][8][4];
#pragma unroll
    for (int i = 0; i < 2; i++)
#pragma unroll
        for (int j = 0; j < 8; j++)
#pragma unroll
            for (int q = 0; q < 4; q++) acc[i][j][q] = 0.f;

    const int KT = K / BK;

    auto load_stage = [&](int s, int k0) {
        __nv_bfloat16* base = smem + s * STAGE_;
#pragma unroll
        for (int p = 0; p < 2; p++) {
            int r = lr + p * 64;
            size_t soA = (size_t)p * 64 * lda + k0;
            size_t soB = (size_t)p * 64 * ldb + k0;
            cp16(base + r * LDSM_ + lc,              srcA_h + soA);
            cp16(base + TILE_ + r * LDSM_ + lc,      srcA_l + soA);
            cp16(base + 2 * TILE_ + r * LDSM_ + lc,  srcB_h + soB);
            cp16(base + 3 * TILE_ + r * LDSM_ + lc,  srcB_l + soB);
        }
    };

    load_stage(0, 0);
    cp_commit();

    for (int it = 0; it < KT; it++) {
        if (it + 1 < KT) {
            load_stage((it + 1) & 1, (it + 1) * BK);
            cp_commit();
            cp_wait<1>();
        } else {
            cp_wait<0>();
        }
        __syncthreads();

        const __nv_bfloat16* base = smem + (it & 1) * STAGE_;
        const __nv_bfloat16* sAh = base;
        const __nv_bfloat16* sAl = base + TILE_;
        const __nv_bfloat16* sBh = base + 2 * TILE_;
        const __nv_bfloat16* sBl = base + 3 * TILE_;

        uint32_t ah[2][2][4], al[2][2][4], bh[2][8][2], bl[2][8][2];

        auto ldf = [&](int q, int ks) {
            int arow_off = lane & 15;
            int akc = ks * 16 + (lane >> 4) * 8;
#pragma unroll
            for (int mt = 0; mt < 2; mt++) {
                int arow = wm * 32 + mt * 16 + arow_off;
                ldsm_x4(ah[q][mt][0], ah[q][mt][1], ah[q][mt][2], ah[q][mt][3],
                        sAh + arow * LDSM_ + akc);
                ldsm_x4(al[q][mt][0], al[q][mt][1], al[q][mt][2], al[q][mt][3],
                        sAl + arow * LDSM_ + akc);
            }
            int nrow_off = (lane & 7) + ((lane >> 4) & 1) * 8;
            int bkc = ks * 16 + ((lane >> 3) & 1) * 8;
#pragma unroll
            for (int ntp = 0; ntp < 4; ntp++) {
                int nrow = wn * 64 + ntp * 16 + nrow_off;
                ldsm_x4(bh[q][2 * ntp][0], bh[q][2 * ntp][1],
                        bh[q][2 * ntp + 1][0], bh[q][2 * ntp + 1][1],
                        sBh + nrow * LDSM_ + bkc);
                ldsm_x4(bl[q][2 * ntp][0], bl[q][2 * ntp][1],
                        bl[q][2 * ntp + 1][0], bl[q][2 * ntp + 1][1],
                        sBl + nrow * LDSM_ + bkc);
            }
        };

        ldf(0, 0);
#pragma unroll
        for (int ks = 0; ks < 2; ks++) {
            if (ks == 0) ldf(1, 1);     // prefetch next k16 fragments during ks=0 MMAs
#pragma unroll
            for (int mt = 0; mt < 2; mt++)
#pragma unroll
                for (int nt = 0; nt < 8; nt++) {
                    mma_bf16(acc[mt][nt], ah[ks][mt], bh[ks][nt]);
                    mma_bf16(acc[mt][nt], ah[ks][mt], bl[ks][nt]);
                    mma_bf16(acc[mt][nt], al[ks][mt], bh[ks][nt]);
                }
        }
        __syncthreads();
    }

    // ---------- epilogue ----------
#pragma unroll
    for (int mt = 0; mt < 2; mt++) {
        int row = bm + wm * 32 + mt * 16 + (lane >> 2);
#pragma unroll
        for (int nt = 0; nt < 8; nt++) {
            int col = bn + wn * 64 + nt * 8 + (lane & 3) * 2;
            if (col >= N) continue;
#pragma unroll
            for (int half = 0; half < 2; half++) {
                int r = row + half * 8;
                float v0 = acc[mt][nt][2 * half + 0];
                float v1 = acc[mt][nt][2 * half + 1];
                if (EPI == 1) {
                    v0 += bias[col];
                    v1 += bias[col + 1];
                    v0 = (v0 > 20.f) ? v0 : log1pf(expf(v0));
                    v1 = (v1 > 20.f) ? v1 : log1pf(expf(v1));
                }
                float2 st; st.x = v0; st.y = v1;
                *reinterpret_cast<float2*>(C + (size_t)r * ldc + col) = st;
            }
        }
    }
}

// ---------------- K3 split-K reduce: sum partials, emit fp32 + bf16 hi/lo --------------
__global__ void k3_reduce_kernel()
{
    int i = blockIdx.x * blockDim.x + threadIdx.x;
    float s = 0.f;
#pragma unroll
    for (int z = 0; z < KSPL; z++)
        s += g_part[(size_t)z * MROWS * XDBL_W + i];
    g_xdbl[i] = s;
    __nv_bfloat16 h = __float2bfloat16(s);
    g_xdh[i] = h;
    g_xdl[i] = __float2bfloat16(s - __bfloat162float(h));
}

// ---------------- depthwise conv + bias + silu; dual-format output ----------------
__global__ void conv_silu_kernel(const float* __restrict__ cw,
                                 const float* __restrict__ cb)
{
    int d = blockIdx.x * blockDim.x + threadIdx.x;
    int m = blockIdx.y;
    int l = m & (SEQ - 1);

    float acc = cb[d];
#pragma unroll
    for (int k = 0; k < 4; k++) {
        int ll = l - 3 + k;
        if (ll >= 0)
            acc = fmaf(cw[d * 4 + k], g_xz[(size_t)(m - 3 + k) * E2 + d], acc);
    }
    float s = acc / (1.f + expf(-acc));
    size_t o = (size_t)m * DI + d;
    g_x[o] = s;
    __nv_bfloat16 h = __float2bfloat16(s);
    g_xh[o] = h;
    g_xl[o] = __float2bfloat16(s - __bfloat162float(h));
}

// ---------------- selective scan: 8 threads/channel, 2 states each ---------------------
__global__ void scan_kernel(const float* __restrict__ A_log,
                            const float* __restrict__ Dp)
{
    int t = blockIdx.x * blockDim.x + threadIdx.x;
    int chan = t >> 3;
    int sub  = t & 7;
    int b = chan >> 11;
    int d = chan & (DI - 1);

    float A0 = -expf(A_log[d * DS + sub * 2 + 0]);
    float A1 = -expf(A_log[d * DS + sub * 2 + 1]);
    float Dd = Dp[d];

    float h0 = 0.f, h1 = 0.f;
    size_t mb = (size_t)b * SEQ;

    float dt = g_delta[mb * DI + d];
    float xv = g_x[mb * DI + d];
    float zv = g_xz[mb * E2 + DI + d];
    float2 Bv = *reinterpret_cast<const float2*>(g_xdbl + mb * XDBL_W + DTR + sub * 2);
    float2 Cv = *reinterpret_cast<const float2*>(g_xdbl + mb * XDBL_W + DTR + DS + sub * 2);

    for (int l = 0; l < SEQ; l++) {
        float dtn = 0.f, xvn = 0.f, zvn = 0.f;
        float2 Bn = make_float2(0.f, 0.f), Cn = Bn;
        if (l + 1 < SEQ) {
            size_t m2 = mb + l + 1;
            dtn = g_delta[m2 * DI + d];
            xvn = g_x[m2 * DI + d];
            zvn = g_xz[m2 * E2 + DI + d];
            Bn = *reinterpret_cast<const float2*>(g_xdbl + m2 * XDBL_W + DTR + sub * 2);
            Cn = *reinterpret_cast<const float2*>(g_xdbl + m2 * XDBL_W + DTR + DS + sub * 2);
        }

        float dx = dt * xv;
        float e0 = __expf(dt * A0);
        float e1 = __expf(dt * A1);
        h0 = fmaf(e0, h0, dx * Bv.x);
        h1 = fmaf(e1, h1, dx * Bv.y);
        float part = fmaf(h1, Cv.y, h0 * Cv.x);
        part += __shfl_xor_sync(0xFFFFFFFFu, part, 1);
        part += __shfl_xor_sync(0xFFFFFFFFu, part, 2);
        part += __shfl_xor_sync(0xFFFFFFFFu, part, 4);

        if (sub == 0) {
            float sz = zv / (1.f + __expf(-zv));
            float yv = (part + Dd * xv) * sz;
            size_t o = (mb + l) * DI + d;
            __nv_bfloat16 hh = __float2bfloat16(yv);
            g_yh[o] = hh;
            g_yl[o] = __float2bfloat16(yv - __bfloat162float(hh));
        }

        dt = dtn; xv = xvn; zv = zvn; Bv = Bn; Cv = Cn;
    }
}

// ---------------- launch ----------------
extern "C" void kernel_launch(void* const* d_in, const int* in_sizes, int n_in,
                              void* d_out, int out_size)
{
    const float* hs        = (const float*)d_in[0];
    const float* in_proj_w = (const float*)d_in[1];
    const float* conv_w    = (const float*)d_in[2];
    const float* conv_b    = (const float*)d_in[3];
    const float* x_proj_w  = (const float*)d_in[4];
    const float* dt_proj_w = (const float*)d_in[5];
    const float* dt_proj_b = (const float*)d_in[6];
    const float* A_log     = (const float*)d_in[7];
    const float* Dp        = (const float*)d_in[8];
    const float* out_w     = (const float*)d_in[9];
    float* out = (float*)d_out;

    float *p_xz, *p_xdbl, *p_delta, *p_part;
    cudaGetSymbolAddress((void**)&p_xz,    g_xz);
    cudaGetSymbolAddress((void**)&p_xdbl,  g_xdbl);
    cudaGetSymbolAddress((void**)&p_delta, g_delta);
    cudaGetSymbolAddress((void**)&p_part,  g_part);

    __nv_bfloat16 *p_hs_h, *p_hs_l, *p_w1_h, *p_w1_l, *p_xp_h, *p_xp_l;
    __nv_bfloat16 *p_dw_h, *p_dw_l, *p_ow_h, *p_ow_l;
    __nv_bfloat16 *p_xh, *p_xl, *p_xdh, *p_xdl, *p_yh, *p_yl;
    cudaGetSymbolAddress((void**)&p_hs_h, g_hs_h);
    cudaGetSymbolAddress((void**)&p_hs_l, g_hs_l);
    cudaGetSymbolAddress((void**)&p_w1_h, g_w1_h);
    cudaGetSymbolAddress((void**)&p_w1_l, g_w1_l);
    cudaGetSymbolAddress((void**)&p_xp_h, g_xp_h);
    cudaGetSymbolAddress((void**)&p_xp_l, g_xp_l);
    cudaGetSymbolAddress((void**)&p_dw_h, g_dw_h);
    cudaGetSymbolAddress((void**)&p_dw_l, g_dw_l);
    cudaGetSymbolAddress((void**)&p_ow_h, g_ow_h);
    cudaGetSymbolAddress((void**)&p_ow_l, g_ow_l);
    cudaGetSymbolAddress((void**)&p_xh, g_xh);
    cudaGetSymbolAddress((void**)&p_xl, g_xl);
    cudaGetSymbolAddress((void**)&p_xdh, g_xdh);
    cudaGetSymbolAddress((void**)&p_xdl, g_xdl);
    cudaGetSymbolAddress((void**)&p_yh, g_yh);
    cudaGetSymbolAddress((void**)&p_yl, g_yl);

    cudaFuncSetAttribute(gemm_bf<0>, cudaFuncAttributeMaxDynamicSharedMemorySize, SMEM_BYTES);
    cudaFuncSetAttribute(gemm_bf<1>, cudaFuncAttributeMaxDynamicSharedMemorySize, SMEM_BYTES);

    // C0: conversions (fp32 -> bf16 hi/lo)
    {
        int n;
        n = MROWS * DM;
        cvt_kernel<<<n / 4 / 256, 256>>>(hs, p_hs_h, p_hs_l, n, n);
        n = E2 * DM;
        cvt_kernel<<<n / 4 / 256, 256>>>(in_proj_w, p_w1_h, p_w1_l, n, n);
        cvt_kernel<<<128 * DI / 4 / 256, 256>>>(x_proj_w, p_xp_h, p_xp_l, 96 * DI, 128 * DI);
        n = DI * DTR;
        cvt_kernel<<<n / 4 / 256, 256>>>(dt_proj_w, p_dw_h, p_dw_l, n, n);
        n = DM * DI;
        cvt_kernel<<<n / 4 / 256, 256>>>(out_w, p_ow_h, p_ow_l, n, n);
    }

    // K1: xz = hs . in_proj_w^T   (4096 x 4096 x 1024)
    gemm_bf<0><<<dim3(E2 / 128, MROWS / 128, 1), 256, SMEM_BYTES>>>(
        p_hs_h, p_hs_l, DM, p_w1_h, p_w1_l, DM, p_xz, E2, MROWS, E2, DM, 0, 0, nullptr);

    // K2: depthwise conv + bias + silu
    conv_silu_kernel<<<dim3(DI / 256, MROWS), 256>>>(conv_w, conv_b);

    // K3: x_dbl partials = x . x_proj_w^T  (4096 x 96 x 2048), split-K x8
    gemm_bf<0><<<dim3(1, MROWS / 128, KSPL), 256, SMEM_BYTES>>>(
        p_xh, p_xl, DI, p_xp_h, p_xp_l, DI, p_part, XDBL_W, MROWS, XDBL_W, DI / KSPL,
        DI / KSPL, (size_t)MROWS * XDBL_W, nullptr);
    k3_reduce_kernel<<<MROWS * XDBL_W / 256, 256>>>();

    // K4: delta = softplus(x_dbl[:, :64] . dt_proj_w^T + b)   (4096 x 2048 x 64)
    gemm_bf<1><<<dim3(DI / 128, MROWS / 128, 1), 256, SMEM_BYTES>>>(
        p_xdh, p_xdl, XDBL_W, p_dw_h, p_dw_l, DTR, p_delta, DI, MROWS, DI, DTR,
        0, 0, dt_proj_b);

    // K5: selective scan + gating
    scan_kernel<<<128, 256>>>(A_log, Dp);

    // K6: out = y . out_w^T       (4096 x 1024 x 2048)
    gemm_bf<0><<<dim3(DM / 128, MROWS / 128, 1), 256, SMEM_BYTES>>>(
        p_yh, p_yl, DI, p_ow_h, p_ow_l, DI, out, DM, MROWS, DM, DI, 0, 0, nullptr);
}

// round 7
// speedup vs baseline: 2.8801x; 1.2058x over previous
#include <cuda_runtime.h>
#include <cuda_fp16.h>
#include <math.h>
#include <stdint.h>

// ---------------- problem constants ----------------
#define B_SZ   2
#define SEQ    2048
#define DM     1024
#define DI     2048
#define DS     16
#define DTR    64
#define MROWS  (B_SZ * SEQ)      // 4096
#define E2     (2 * DI)          // 4096
#define XDBL_W 96
#define KSPL   8                 // split-K factor for K3

// ---------------- scratch (device globals) ----------------
static __device__ float g_xz   [(size_t)MROWS * E2];
static __device__ float g_x    [(size_t)MROWS * DI];
static __device__ float g_xdbl [(size_t)MROWS * XDBL_W];
static __device__ float g_delta[(size_t)MROWS * DI];
static __device__ float g_part [(size_t)KSPL * MROWS * XDBL_W];

static __device__ __half g_hs [(size_t)MROWS * DM];
static __device__ __half g_w1 [(size_t)E2 * DM];
static __device__ __half g_xp [(size_t)128 * DI];      // x_proj padded 96->128 rows
static __device__ __half g_dw [(size_t)DI * DTR];
static __device__ __half g_ow [(size_t)DM * DI];
static __device__ __half g_xh [(size_t)MROWS * DI];    // conv output fp16
static __device__ __half g_xdh[(size_t)MROWS * XDBL_W];// x_dbl fp16
static __device__ __half g_yh [(size_t)MROWS * DI];    // scan output fp16

// ---------------- tensor-core helpers ----------------
__device__ __forceinline__ void ldsm_x4(uint32_t& r0, uint32_t& r1, uint32_t& r2, uint32_t& r3,
                                        const __half* p)
{
    uint32_t addr = (uint32_t)__cvta_generic_to_shared(p);
    asm volatile("ldmatrix.sync.aligned.m8n8.x4.shared.b16 {%0,%1,%2,%3}, [%4];\n"
                 : "=r"(r0), "=r"(r1), "=r"(r2), "=r"(r3) : "r"(addr));
}

__device__ __forceinline__ void mma_f16(float* c, const uint32_t* a, const uint32_t* b)
{
    asm volatile(
        "mma.sync.aligned.m16n8k16.row.col.f32.f16.f16.f32 "
        "{%0,%1,%2,%3}, {%4,%5,%6,%7}, {%8,%9}, {%0,%1,%2,%3};\n"
        : "+f"(c[0]), "+f"(c[1]), "+f"(c[2]), "+f"(c[3])
        : "r"(a[0]), "r"(a[1]), "r"(a[2]), "r"(a[3]), "r"(b[0]), "r"(b[1]));
}

__device__ __forceinline__ void cp16(void* dst, const void* src)
{
    uint32_t d = (uint32_t)__cvta_generic_to_shared(dst);
    asm volatile("cp.async.cg.shared.global [%0], [%1], 16;\n" :: "r"(d), "l"(src));
}
__device__ __forceinline__ void cp_commit() { asm volatile("cp.async.commit_group;\n"); }
template<int N>
__device__ __forceinline__ void cp_wait()   { asm volatile("cp.async.wait_group %0;\n" :: "n"(N)); }

// ---------------- fp32 -> fp16 conversion ----------------
__global__ void cvt_kernel(const float* __restrict__ src,
                           __half* __restrict__ dst,
                           int n_valid, int n_total)
{
    int i4 = (blockIdx.x * blockDim.x + threadIdx.x) * 4;
    if (i4 >= n_total) return;
    float4 v = make_float4(0.f, 0.f, 0.f, 0.f);
    if (i4 < n_valid) v = *reinterpret_cast<const float4*>(src + i4);
    __half h[4];
    h[0] = __float2half_rn(v.x);
    h[1] = __float2half_rn(v.y);
    h[2] = __float2half_rn(v.z);
    h[3] = __float2half_rn(v.w);
    *reinterpret_cast<uint2*>(dst + i4) = *reinterpret_cast<uint2*>(h);
}

// ---------------- fp16 HMMA GEMM, 3-stage cp.async, 2 CTAs/SM, frag dbl-buffer ---------
// C[M,N] = A[M,K] * B[N,K]^T (single-term fp16, fp32 accumulate)
// 128x128x32 block tile, 8 warps (4x2), warp tile 32x64 (2x8 m16n8k16 frags).
// blockIdx.z: split-K chunk (A,B advanced z*kzo elems; C by z*czs elems).
// EPI==1: C = softplus(C + bias[col])
#define BK     32
#define LDSMH  40                      // padded row stride (halfs), conflict-free ldmatrix
#define TILEH  (128 * LDSMH)           // halfs per tile
#define STAGEH (2 * TILEH)             // A | B
#define NST    3
#define SMEM_BYTES (NST * STAGEH * (int)sizeof(__half))   // 61440

template<int EPI>
__global__ __launch_bounds__(256, 2)
void gemm_h(const __half* __restrict__ A, int lda,
            const __half* __restrict__ B, int ldb,
            float* __restrict__ C, int ldc,
            int M, int N, int K,
            int kzo, size_t czs,
            const float* __restrict__ bias)
{
    extern __shared__ __half smem[];

    const int tid  = threadIdx.x;
    const int lane = tid & 31;
    const int wid  = tid >> 5;
    const int wm   = wid & 3;
    const int wn   = wid >> 2;

    const int bm = blockIdx.y * 128;
    const int bn = blockIdx.x * 128;

    A += (size_t)blockIdx.z * kzo;
    B += (size_t)blockIdx.z * kzo;
    C += (size_t)blockIdx.z * czs;

    // loader: each thread: 2 rows (tid>>2, +64), 8 halfs (16B) at slot (tid&3)*8
    const int lrow = tid >> 2;
    const int lslot = (tid & 3) * 8;

    float acc[2][8][4];
#pragma unroll
    for (int i = 0; i < 2; i++)
#pragma unroll
        for (int j = 0; j < 8; j++)
#pragma unroll
            for (int q = 0; q < 4; q++) acc[i][j][q] = 0.f;

    const int KT = K / BK;

    auto load_stage = [&](int s, int kt) {
        __half* sA = smem + s * STAGEH;
        __half* sB = sA + TILEH;
        int k0 = kt * BK;
#pragma unroll
        for (int p = 0; p < 2; p++) {
            int r = lrow + p * 64;
            cp16(sA + r * LDSMH + lslot, A + (size_t)(bm + r) * lda + k0 + lslot);
            cp16(sB + r * LDSMH + lslot, B + (size_t)(bn + r) * ldb + k0 + lslot);
        }
    };

    load_stage(0, 0);
    cp_commit();
    if (KT > 1) { load_stage(1, 1); cp_commit(); }

    for (int it = 0; it < KT; it++) {
        if (it + 2 < KT) {
            load_stage((it + 2) % NST, it + 2);
            cp_commit();
            cp_wait<2>();
        } else if (it + 1 < KT) {
            cp_wait<1>();
        } else {
            cp_wait<0>();
        }
        __syncthreads();

        const __half* sA = smem + (it % NST) * STAGEH;
        const __half* sB = sA + TILEH;

        uint32_t af[2][2][4], bf[2][8][2];

        auto ldf = [&](int q, int ks) {
            int arow_off = lane & 15;
            int akc = ks * 16 + (lane >> 4) * 8;
#pragma unroll
            for (int mt = 0; mt < 2; mt++) {
                int arow = wm * 32 + mt * 16 + arow_off;
                ldsm_x4(af[q][mt][0], af[q][mt][1], af[q][mt][2], af[q][mt][3],
                        sA + arow * LDSMH + akc);
            }
            int nrow_off = (lane & 7) + ((lane >> 4) & 1) * 8;
            int bkc = ks * 16 + ((lane >> 3) & 1) * 8;
#pragma unroll
            for (int ntp = 0; ntp < 4; ntp++) {
                int nrow = wn * 64 + ntp * 16 + nrow_off;
                ldsm_x4(bf[q][2 * ntp][0], bf[q][2 * ntp][1],
                        bf[q][2 * ntp + 1][0], bf[q][2 * ntp + 1][1],
                        sB + nrow * LDSMH + bkc);
            }
        };

        ldf(0, 0);
#pragma unroll
        for (int ks = 0; ks < 2; ks++) {
            if (ks == 0) ldf(1, 1);     // prefetch ks=1 fragments during ks=0 MMAs
#pragma unroll
            for (int mt = 0; mt < 2; mt++)
#pragma unroll
                for (int nt = 0; nt < 8; nt++)
                    mma_f16(acc[mt][nt], af[ks][mt], bf[ks][nt]);
        }
        __syncthreads();
    }

    // ---------- epilogue ----------
#pragma unroll
    for (int mt = 0; mt < 2; mt++) {
        int row = bm + wm * 32 + mt * 16 + (lane >> 2);
#pragma unroll
        for (int nt = 0; nt < 8; nt++) {
            int col = bn + wn * 64 + nt * 8 + (lane & 3) * 2;
            if (col >= N) continue;
#pragma unroll
            for (int half_ = 0; half_ < 2; half_++) {
                int r = row + half_ * 8;
                float v0 = acc[mt][nt][2 * half_ + 0];
                float v1 = acc[mt][nt][2 * half_ + 1];
                if (EPI == 1) {
                    v0 += bias[col];
                    v1 += bias[col + 1];
                    v0 = (v0 > 20.f) ? v0 : log1pf(expf(v0));
                    v1 = (v1 > 20.f) ? v1 : log1pf(expf(v1));
                }
                float2 st; st.x = v0; st.y = v1;
                *reinterpret_cast<float2*>(C + (size_t)r * ldc + col) = st;
            }
        }
    }
}

// ---------------- K3 split-K reduce: sum partials, emit fp32 + fp16 --------------------
__global__ void k3_reduce_kernel()
{
    int i = blockIdx.x * blockDim.x + threadIdx.x;
    float s = 0.f;
#pragma unroll
    for (int z = 0; z < KSPL; z++)
        s += g_part[(size_t)z * MROWS * XDBL_W + i];
    g_xdbl[i] = s;
    g_xdh[i] = __float2half_rn(s);
}

// ---------------- depthwise conv + bias + silu; fp32 + fp16 output ---------------------
__global__ void conv_silu_kernel(const float* __restrict__ cw,
                                 const float* __restrict__ cb)
{
    int d = blockIdx.x * blockDim.x + threadIdx.x;
    int m = blockIdx.y;
    int l = m & (SEQ - 1);

    float acc = cb[d];
#pragma unroll
    for (int k = 0; k < 4; k++) {
        int ll = l - 3 + k;
        if (ll >= 0)
            acc = fmaf(cw[d * 4 + k], g_xz[(size_t)(m - 3 + k) * E2 + d], acc);
    }
    float s = acc / (1.f + expf(-acc));
    size_t o = (size_t)m * DI + d;
    g_x[o] = s;
    g_xh[o] = __float2half_rn(s);
}

// ---------------- selective scan: 8 threads/channel, 2 states each ---------------------
__global__ void scan_kernel(const float* __restrict__ A_log,
                            const float* __restrict__ Dp)
{
    int t = blockIdx.x * blockDim.x + threadIdx.x;
    int chan = t >> 3;
    int sub  = t & 7;
    int b = chan >> 11;
    int d = chan & (DI - 1);

    float A0 = -expf(A_log[d * DS + sub * 2 + 0]);
    float A1 = -expf(A_log[d * DS + sub * 2 + 1]);
    float Dd = Dp[d];

    float h0 = 0.f, h1 = 0.f;
    size_t mb = (size_t)b * SEQ;

    float dt = g_delta[mb * DI + d];
    float xv = g_x[mb * DI + d];
    float zv = g_xz[mb * E2 + DI + d];
    float2 Bv = *reinterpret_cast<const float2*>(g_xdbl + mb * XDBL_W + DTR + sub * 2);
    float2 Cv = *reinterpret_cast<const float2*>(g_xdbl + mb * XDBL_W + DTR + DS + sub * 2);

    for (int l = 0; l < SEQ; l++) {
        float dtn = 0.f, xvn = 0.f, zvn = 0.f;
        float2 Bn = make_float2(0.f, 0.f), Cn = Bn;
        if (l + 1 < SEQ) {
            size_t m2 = mb + l + 1;
            dtn = g_delta[m2 * DI + d];
            xvn = g_x[m2 * DI + d];
            zvn = g_xz[m2 * E2 + DI + d];
            Bn = *reinterpret_cast<const float2*>(g_xdbl + m2 * XDBL_W + DTR + sub * 2);
            Cn = *reinterpret_cast<const float2*>(g_xdbl + m2 * XDBL_W + DTR + DS + sub * 2);
        }

        float dx = dt * xv;
        float e0 = __expf(dt * A0);
        float e1 = __expf(dt * A1);
        h0 = fmaf(e0, h0, dx * Bv.x);
        h1 = fmaf(e1, h1, dx * Bv.y);
        float part = fmaf(h1, Cv.y, h0 * Cv.x);
        part += __shfl_xor_sync(0xFFFFFFFFu, part, 1);
        part += __shfl_xor_sync(0xFFFFFFFFu, part, 2);
        part += __shfl_xor_sync(0xFFFFFFFFu, part, 4);

        if (sub == 0) {
            float sz = zv / (1.f + __expf(-zv));
            float yv = (part + Dd * xv) * sz;
            g_yh[(mb + l) * DI + d] = __float2half_rn(yv);
        }

        dt = dtn; xv = xvn; zv = zvn; Bv = Bn; Cv = Cn;
    }
}

// ---------------- launch ----------------
extern "C" void kernel_launch(void* const* d_in, const int* in_sizes, int n_in,
                              void* d_out, int out_size)
{
    const float* hs        = (const float*)d_in[0];
    const float* in_proj_w = (const float*)d_in[1];
    const float* conv_w    = (const float*)d_in[2];
    const float* conv_b    = (const float*)d_in[3];
    const float* x_proj_w  = (const float*)d_in[4];
    const float* dt_proj_w = (const float*)d_in[5];
    const float* dt_proj_b = (const float*)d_in[6];
    const float* A_log     = (const float*)d_in[7];
    const float* Dp        = (const float*)d_in[8];
    const float* out_w     = (const float*)d_in[9];
    float* out = (float*)d_out;

    float *p_xz, *p_part;
    cudaGetSymbolAddress((void**)&p_xz,    g_xz);
    cudaGetSymbolAddress((void**)&p_part,  g_part);
    float *p_delta;
    cudaGetSymbolAddress((void**)&p_delta, g_delta);

    __half *p_hs, *p_w1, *p_xp, *p_dw, *p_ow, *p_xh, *p_xdh, *p_yh;
    cudaGetSymbolAddress((void**)&p_hs,  g_hs);
    cudaGetSymbolAddress((void**)&p_w1,  g_w1);
    cudaGetSymbolAddress((void**)&p_xp,  g_xp);
    cudaGetSymbolAddress((void**)&p_dw,  g_dw);
    cudaGetSymbolAddress((void**)&p_ow,  g_ow);
    cudaGetSymbolAddress((void**)&p_xh,  g_xh);
    cudaGetSymbolAddress((void**)&p_xdh, g_xdh);
    cudaGetSymbolAddress((void**)&p_yh,  g_yh);

    cudaFuncSetAttribute(gemm_h<0>, cudaFuncAttributeMaxDynamicSharedMemorySize, SMEM_BYTES);
    cudaFuncSetAttribute(gemm_h<1>, cudaFuncAttributeMaxDynamicSharedMemorySize, SMEM_BYTES);

    // C0: conversions (fp32 -> fp16)
    {
        int n;
        n = MROWS * DM;
        cvt_kernel<<<n / 4 / 256, 256>>>(hs, p_hs, n, n);
        n = E2 * DM;
        cvt_kernel<<<n / 4 / 256, 256>>>(in_proj_w, p_w1, n, n);
        cvt_kernel<<<128 * DI / 4 / 256, 256>>>(x_proj_w, p_xp, 96 * DI, 128 * DI);
        n = DI * DTR;
        cvt_kernel<<<n / 4 / 256, 256>>>(dt_proj_w, p_dw, n, n);
        n = DM * DI;
        cvt_kernel<<<n / 4 / 256, 256>>>(out_w, p_ow, n, n);
    }

    // K1: xz = hs . in_proj_w^T   (4096 x 4096 x 1024)
    gemm_h<0><<<dim3(E2 / 128, MROWS / 128, 1), 256, SMEM_BYTES>>>(
        p_hs, DM, p_w1, DM, p_xz, E2, MROWS, E2, DM, 0, 0, nullptr);

    // K2: depthwise conv + bias + silu
    conv_silu_kernel<<<dim3(DI / 256, MROWS), 256>>>(conv_w, conv_b);

    // K3: x_dbl partials = x . x_proj_w^T  (4096 x 96 x 2048), split-K x8
    gemm_h<0><<<dim3(1, MROWS / 128, KSPL), 256, SMEM_BYTES>>>(
        p_xh, DI, p_xp, DI, p_part, XDBL_W, MROWS, XDBL_W, DI / KSPL,
        DI / KSPL, (size_t)MROWS * XDBL_W, nullptr);
    k3_reduce_kernel<<<MROWS * XDBL_W / 256, 256>>>();

    // K4: delta = softplus(x_dbl[:, :64] . dt_proj_w^T + b)   (4096 x 2048 x 64)
    gemm_h<1><<<dim3(DI / 128, MROWS / 128, 1), 256, SMEM_BYTES>>>(
        p_xdh, XDBL_W, p_dw, DTR, p_delta, DI, MROWS, DI, DTR, 0, 0, dt_proj_b);

    // K5: selective scan + gating
    scan_kernel<<<128, 256>>>(A_log, Dp);

    // K6: out = y . out_w^T       (4096 x 1024 x 2048)
    gemm_h<0><<<dim3(DM / 128, MROWS / 128, 1), 256, SMEM_BYTES>>>(
        p_yh, DI, p_ow, DI, out, DM, MROWS, DM, DI, 0, 0, nullptr);
}

// round 8
// speedup vs baseline: 6.3879x; 2.2180x over previous
#include <cuda_runtime.h>
#include <cuda_fp16.h>
#include <math.h>
#include <stdint.h>

// ---------------- problem constants ----------------
#define B_SZ   2
#define SEQ    2048
#define DM     1024
#define DI     2048
#define DS     16
#define DTR    64
#define MROWS  (B_SZ * SEQ)      // 4096
#define E2     (2 * DI)          // 4096
#define XDBL_W 96
#define KSPL   8                 // split-K factor for K3
#define NCHK   8                 // scan chunks
#define CHKL   (SEQ / NCHK)      // 256 steps per chunk
#define NCHAN  (B_SZ * DI)       // 4096

// ---------------- scratch (device globals) ----------------
static __device__ float g_xz   [(size_t)MROWS * E2];
static __device__ float g_x    [(size_t)MROWS * DI];
static __device__ float g_xdbl [(size_t)MROWS * XDBL_W];
static __device__ float g_delta[(size_t)MROWS * DI];
static __device__ float g_part [(size_t)KSPL * MROWS * XDBL_W];

// chunked-scan state: per (chunk, chan, sub, state<2>)
static __device__ float g_P   [(size_t)NCHK * NCHAN * 16];
static __device__ float g_hend[(size_t)NCHK * NCHAN * 16];
static __device__ float g_hin [(size_t)NCHK * NCHAN * 16];

static __device__ __half g_hs [(size_t)MROWS * DM];
static __device__ __half g_w1 [(size_t)E2 * DM];
static __device__ __half g_xp [(size_t)128 * DI];      // x_proj padded 96->128 rows
static __device__ __half g_dw [(size_t)DI * DTR];
static __device__ __half g_ow [(size_t)DM * DI];
static __device__ __half g_xh [(size_t)MROWS * DI];    // conv output fp16
static __device__ __half g_xdh[(size_t)MROWS * XDBL_W];// x_dbl fp16
static __device__ __half g_yh [(size_t)MROWS * DI];    // scan output fp16

#define CIX(c, chan, sub) (((((size_t)(c)) * NCHAN + (chan)) * 8 + (sub)) * 2)

// ---------------- tensor-core helpers ----------------
__device__ __forceinline__ void ldsm_x4(uint32_t& r0, uint32_t& r1, uint32_t& r2, uint32_t& r3,
                                        const __half* p)
{
    uint32_t addr = (uint32_t)__cvta_generic_to_shared(p);
    asm volatile("ldmatrix.sync.aligned.m8n8.x4.shared.b16 {%0,%1,%2,%3}, [%4];\n"
                 : "=r"(r0), "=r"(r1), "=r"(r2), "=r"(r3) : "r"(addr));
}

__device__ __forceinline__ void mma_f16(float* c, const uint32_t* a, const uint32_t* b)
{
    asm volatile(
        "mma.sync.aligned.m16n8k16.row.col.f32.f16.f16.f32 "
        "{%0,%1,%2,%3}, {%4,%5,%6,%7}, {%8,%9}, {%0,%1,%2,%3};\n"
        : "+f"(c[0]), "+f"(c[1]), "+f"(c[2]), "+f"(c[3])
        : "r"(a[0]), "r"(a[1]), "r"(a[2]), "r"(a[3]), "r"(b[0]), "r"(b[1]));
}

__device__ __forceinline__ void cp16(void* dst, const void* src)
{
    uint32_t d = (uint32_t)__cvta_generic_to_shared(dst);
    asm volatile("cp.async.cg.shared.global [%0], [%1], 16;\n" :: "r"(d), "l"(src));
}
__device__ __forceinline__ void cp_commit() { asm volatile("cp.async.commit_group;\n"); }
template<int N>
__device__ __forceinline__ void cp_wait()   { asm volatile("cp.async.wait_group %0;\n" :: "n"(N)); }

// ---------------- fp32 -> fp16 conversion ----------------
__global__ void cvt_kernel(const float* __restrict__ src,
                           __half* __restrict__ dst,
                           int n_valid, int n_total)
{
    int i4 = (blockIdx.x * blockDim.x + threadIdx.x) * 4;
    if (i4 >= n_total) return;
    float4 v = make_float4(0.f, 0.f, 0.f, 0.f);
    if (i4 < n_valid) v = *reinterpret_cast<const float4*>(src + i4);
    __half h[4];
    h[0] = __float2half_rn(v.x);
    h[1] = __float2half_rn(v.y);
    h[2] = __float2half_rn(v.z);
    h[3] = __float2half_rn(v.w);
    *reinterpret_cast<uint2*>(dst + i4) = *reinterpret_cast<uint2*>(h);
}

// ---------------- fp16 HMMA GEMM, 3-stage cp.async, 2 CTAs/SM, frag dbl-buffer ---------
#define BK     32
#define LDSMH  40
#define TILEH  (128 * LDSMH)
#define STAGEH (2 * TILEH)
#define NST    3
#define SMEM_BYTES (NST * STAGEH * (int)sizeof(__half))   // 61440

template<int EPI>
__global__ __launch_bounds__(256, 2)
void gemm_h(const __half* __restrict__ A, int lda,
            const __half* __restrict__ B, int ldb,
            float* __restrict__ C, int ldc,
            int M, int N, int K,
            int kzo, size_t czs,
            const float* __restrict__ bias)
{
    extern __shared__ __half smem[];

    const int tid  = threadIdx.x;
    const int lane = tid & 31;
    const int wid  = tid >> 5;
    const int wm   = wid & 3;
    const int wn   = wid >> 2;

    const int bm = blockIdx.y * 128;
    const int bn = blockIdx.x * 128;

    A += (size_t)blockIdx.z * kzo;
    B += (size_t)blockIdx.z * kzo;
    C += (size_t)blockIdx.z * czs;

    const int lrow = tid >> 2;
    const int lslot = (tid & 3) * 8;

    float acc[2][8][4];
#pragma unroll
    for (int i = 0; i < 2; i++)
#pragma unroll
        for (int j = 0; j < 8; j++)
#pragma unroll
            for (int q = 0; q < 4; q++) acc[i][j][q] = 0.f;

    const int KT = K / BK;

    auto load_stage = [&](int s, int kt) {
        __half* sA = smem + s * STAGEH;
        __half* sB = sA + TILEH;
        int k0 = kt * BK;
#pragma unroll
        for (int p = 0; p < 2; p++) {
            int r = lrow + p * 64;
            cp16(sA + r * LDSMH + lslot, A + (size_t)(bm + r) * lda + k0 + lslot);
            cp16(sB + r * LDSMH + lslot, B + (size_t)(bn + r) * ldb + k0 + lslot);
        }
    };

    load_stage(0, 0);
    cp_commit();
    if (KT > 1) { load_stage(1, 1); cp_commit(); }

    for (int it = 0; it < KT; it++) {
        if (it + 2 < KT) {
            load_stage((it + 2) % NST, it + 2);
            cp_commit();
            cp_wait<2>();
        } else if (it + 1 < KT) {
            cp_wait<1>();
        } else {
            cp_wait<0>();
        }
        __syncthreads();

        const __half* sA = smem + (it % NST) * STAGEH;
        const __half* sB = sA + TILEH;

        uint32_t af[2][2][4], bf[2][8][2];

        auto ldf = [&](int q, int ks) {
            int arow_off = lane & 15;
            int akc = ks * 16 + (lane >> 4) * 8;
#pragma unroll
            for (int mt = 0; mt < 2; mt++) {
                int arow = wm * 32 + mt * 16 + arow_off;
                ldsm_x4(af[q][mt][0], af[q][mt][1], af[q][mt][2], af[q][mt][3],
                        sA + arow * LDSMH + akc);
            }
            int nrow_off = (lane & 7) + ((lane >> 4) & 1) * 8;
            int bkc = ks * 16 + ((lane >> 3) & 1) * 8;
#pragma unroll
            for (int ntp = 0; ntp < 4; ntp++) {
                int nrow = wn * 64 + ntp * 16 + nrow_off;
                ldsm_x4(bf[q][2 * ntp][0], bf[q][2 * ntp][1],
                        bf[q][2 * ntp + 1][0], bf[q][2 * ntp + 1][1],
                        sB + nrow * LDSMH + bkc);
            }
        };

        ldf(0, 0);
#pragma unroll
        for (int ks = 0; ks < 2; ks++) {
            if (ks == 0) ldf(1, 1);
#pragma unroll
            for (int mt = 0; mt < 2; mt++)
#pragma unroll
                for (int nt = 0; nt < 8; nt++)
                    mma_f16(acc[mt][nt], af[ks][mt], bf[ks][nt]);
        }
        __syncthreads();
    }

#pragma unroll
    for (int mt = 0; mt < 2; mt++) {
        int row = bm + wm * 32 + mt * 16 + (lane >> 2);
#pragma unroll
        for (int nt = 0; nt < 8; nt++) {
            int col = bn + wn * 64 + nt * 8 + (lane & 3) * 2;
            if (col >= N) continue;
#pragma unroll
            for (int half_ = 0; half_ < 2; half_++) {
                int r = row + half_ * 8;
                float v0 = acc[mt][nt][2 * half_ + 0];
                float v1 = acc[mt][nt][2 * half_ + 1];
                if (EPI == 1) {
                    v0 += bias[col];
                    v1 += bias[col + 1];
                    v0 = (v0 > 20.f) ? v0 : log1pf(expf(v0));
                    v1 = (v1 > 20.f) ? v1 : log1pf(expf(v1));
                }
                float2 st; st.x = v0; st.y = v1;
                *reinterpret_cast<float2*>(C + (size_t)r * ldc + col) = st;
            }
        }
    }
}

// ---------------- K3 split-K reduce ----------------
__global__ void k3_reduce_kernel()
{
    int i = blockIdx.x * blockDim.x + threadIdx.x;
    float s = 0.f;
#pragma unroll
    for (int z = 0; z < KSPL; z++)
        s += g_part[(size_t)z * MROWS * XDBL_W + i];
    g_xdbl[i] = s;
    g_xdh[i] = __float2half_rn(s);
}

// ---------------- depthwise conv + bias + silu ----------------
__global__ void conv_silu_kernel(const float* __restrict__ cw,
                                 const float* __restrict__ cb)
{
    int d = blockIdx.x * blockDim.x + threadIdx.x;
    int m = blockIdx.y;
    int l = m & (SEQ - 1);

    float acc = cb[d];
#pragma unroll
    for (int k = 0; k < 4; k++) {
        int ll = l - 3 + k;
        if (ll >= 0)
            acc = fmaf(cw[d * 4 + k], g_xz[(size_t)(m - 3 + k) * E2 + d], acc);
    }
    float s = acc / (1.f + expf(-acc));
    size_t o = (size_t)m * DI + d;
    g_x[o] = s;
    g_xh[o] = __float2half_rn(s);
}

// ---------------- chunked selective scan ----------------
// Pass A: per (chunk, chan, sub): decay product P and chunk-local end state (h from 0).
__global__ void scan_passA(const float* __restrict__ A_log)
{
    int t = blockIdx.x * blockDim.x + threadIdx.x;   // 0..262143
    int chunk = t >> 15;
    int r = t & 32767;
    int chan = r >> 3;
    int sub  = r & 7;
    int b = chan >> 11;
    int d = chan & (DI - 1);

    float A0 = -expf(A_log[d * DS + sub * 2 + 0]);
    float A1 = -expf(A_log[d * DS + sub * 2 + 1]);

    float h0 = 0.f, h1 = 0.f, P0 = 1.f, P1 = 1.f;
    size_t mb = (size_t)b * SEQ + chunk * CHKL;

    float dt = g_delta[mb * DI + d];
    float xv = g_x[mb * DI + d];
    float2 Bv = *reinterpret_cast<const float2*>(g_xdbl + mb * XDBL_W + DTR + sub * 2);

    for (int l = 0; l < CHKL; l++) {
        float dtn = 0.f, xvn = 0.f;
        float2 Bn = make_float2(0.f, 0.f);
        if (l + 1 < CHKL) {
            size_t m2 = mb + l + 1;
            dtn = g_delta[m2 * DI + d];
            xvn = g_x[m2 * DI + d];
            Bn = *reinterpret_cast<const float2*>(g_xdbl + m2 * XDBL_W + DTR + sub * 2);
        }
        float dx = dt * xv;
        float e0 = __expf(dt * A0);
        float e1 = __expf(dt * A1);
        P0 *= e0;
        P1 *= e1;
        h0 = fmaf(e0, h0, dx * Bv.x);
        h1 = fmaf(e1, h1, dx * Bv.y);
        dt = dtn; xv = xvn; Bv = Bn;
    }

    size_t o = CIX(chunk, chan, sub);
    g_P[o]     = P0;  g_P[o + 1]    = P1;
    g_hend[o]  = h0;  g_hend[o + 1] = h1;
}

// Fix-up: serial compose over chunks (parallel over chan x sub).
__global__ void scan_fixup()
{
    int t = blockIdx.x * blockDim.x + threadIdx.x;   // 0..32767
    int chan = t >> 3;
    int sub  = t & 7;

    float h0 = 0.f, h1 = 0.f;
    {
        size_t o = CIX(0, chan, sub);
        g_hin[o] = 0.f; g_hin[o + 1] = 0.f;
    }
#pragma unroll
    for (int c = 1; c < NCHK; c++) {
        size_t p = CIX(c - 1, chan, sub);
        h0 = fmaf(g_P[p],     h0, g_hend[p]);
        h1 = fmaf(g_P[p + 1], h1, g_hend[p + 1]);
        size_t o = CIX(c, chan, sub);
        g_hin[o] = h0; g_hin[o + 1] = h1;
    }
}

// Pass B: full scan per chunk seeded with h_in; emits gated y (fp16).
__global__ void scan_passB(const float* __restrict__ A_log,
                           const float* __restrict__ Dp)
{
    int t = blockIdx.x * blockDim.x + threadIdx.x;   // 0..262143
    int chunk = t >> 15;
    int r = t & 32767;
    int chan = r >> 3;
    int sub  = r & 7;
    int b = chan >> 11;
    int d = chan & (DI - 1);

    float A0 = -expf(A_log[d * DS + sub * 2 + 0]);
    float A1 = -expf(A_log[d * DS + sub * 2 + 1]);
    float Dd = Dp[d];

    float h0, h1;
    {
        size_t o = CIX(chunk, chan, sub);
        h0 = g_hin[o]; h1 = g_hin[o + 1];
    }
    size_t mb = (size_t)b * SEQ + chunk * CHKL;

    float dt = g_delta[mb * DI + d];
    float xv = g_x[mb * DI + d];
    float zv = g_xz[mb * E2 + DI + d];
    float2 Bv = *reinterpret_cast<const float2*>(g_xdbl + mb * XDBL_W + DTR + sub * 2);
    float2 Cv = *reinterpret_cast<const float2*>(g_xdbl + mb * XDBL_W + DTR + DS + sub * 2);

    for (int l = 0; l < CHKL; l++) {
        float dtn = 0.f, xvn = 0.f, zvn = 0.f;
        float2 Bn = make_float2(0.f, 0.f), Cn = Bn;
        if (l + 1 < CHKL) {
            size_t m2 = mb + l + 1;
            dtn = g_delta[m2 * DI + d];
            xvn = g_x[m2 * DI + d];
            zvn = g_xz[m2 * E2 + DI + d];
            Bn = *reinterpret_cast<const float2*>(g_xdbl + m2 * XDBL_W + DTR + sub * 2);
            Cn = *reinterpret_cast<const float2*>(g_xdbl + m2 * XDBL_W + DTR + DS + sub * 2);
        }

        float dx = dt * xv;
        float e0 = __expf(dt * A0);
        float e1 = __expf(dt * A1);
        h0 = fmaf(e0, h0, dx * Bv.x);
        h1 = fmaf(e1, h1, dx * Bv.y);
        float part = fmaf(h1, Cv.y, h0 * Cv.x);
        part += __shfl_xor_sync(0xFFFFFFFFu, part, 1);
        part += __shfl_xor_sync(0xFFFFFFFFu, part, 2);
        part += __shfl_xor_sync(0xFFFFFFFFu, part, 4);

        if (sub == 0) {
            float sz = zv / (1.f + __expf(-zv));
            float yv = (part + Dd * xv) * sz;
            g_yh[(mb + l) * DI + d] = __float2half_rn(yv);
        }

        dt = dtn; xv = xvn; zv = zvn; Bv = Bn; Cv = Cn;
    }
}

// ---------------- launch ----------------
extern "C" void kernel_launch(void* const* d_in, const int* in_sizes, int n_in,
                              void* d_out, int out_size)
{
    const float* hs        = (const float*)d_in[0];
    const float* in_proj_w = (const float*)d_in[1];
    const float* conv_w    = (const float*)d_in[2];
    const float* conv_b    = (const float*)d_in[3];
    const float* x_proj_w  = (const float*)d_in[4];
    const float* dt_proj_w = (const float*)d_in[5];
    const float* dt_proj_b = (const float*)d_in[6];
    const float* A_log     = (const float*)d_in[7];
    const float* Dp        = (const float*)d_in[8];
    const float* out_w     = (const float*)d_in[9];
    float* out = (float*)d_out;

    float *p_xz, *p_part, *p_delta;
    cudaGetSymbolAddress((void**)&p_xz,    g_xz);
    cudaGetSymbolAddress((void**)&p_part,  g_part);
    cudaGetSymbolAddress((void**)&p_delta, g_delta);

    __half *p_hs, *p_w1, *p_xp, *p_dw, *p_ow, *p_xh, *p_xdh, *p_yh;
    cudaGetSymbolAddress((void**)&p_hs,  g_hs);
    cudaGetSymbolAddress((void**)&p_w1,  g_w1);
    cudaGetSymbolAddress((void**)&p_xp,  g_xp);
    cudaGetSymbolAddress((void**)&p_dw,  g_dw);
    cudaGetSymbolAddress((void**)&p_ow,  g_ow);
    cudaGetSymbolAddress((void**)&p_xh,  g_xh);
    cudaGetSymbolAddress((void**)&p_xdh, g_xdh);
    cudaGetSymbolAddress((void**)&p_yh,  g_yh);

    cudaFuncSetAttribute(gemm_h<0>, cudaFuncAttributeMaxDynamicSharedMemorySize, SMEM_BYTES);
    cudaFuncSetAttribute(gemm_h<1>, cudaFuncAttributeMaxDynamicSharedMemorySize, SMEM_BYTES);

    // C0: conversions (fp32 -> fp16)
    {
        int n;
        n = MROWS * DM;
        cvt_kernel<<<n / 4 / 256, 256>>>(hs, p_hs, n, n);
        n = E2 * DM;
        cvt_kernel<<<n / 4 / 256, 256>>>(in_proj_w, p_w1, n, n);
        cvt_kernel<<<128 * DI / 4 / 256, 256>>>(x_proj_w, p_xp, 96 * DI, 128 * DI);
        n = DI * DTR;
        cvt_kernel<<<n / 4 / 256, 256>>>(dt_proj_w, p_dw, n, n);
        n = DM * DI;
        cvt_kernel<<<n / 4 / 256, 256>>>(out_w, p_ow, n, n);
    }

    // K1: xz = hs . in_proj_w^T   (4096 x 4096 x 1024)
    gemm_h<0><<<dim3(E2 / 128, MROWS / 128, 1), 256, SMEM_BYTES>>>(
        p_hs, DM, p_w1, DM, p_xz, E2, MROWS, E2, DM, 0, 0, nullptr);

    // K2: depthwise conv + bias + silu
    conv_silu_kernel<<<dim3(DI / 256, MROWS), 256>>>(conv_w, conv_b);

    // K3: x_dbl partials = x . x_proj_w^T  (4096 x 96 x 2048), split-K x8
    gemm_h<0><<<dim3(1, MROWS / 128, KSPL), 256, SMEM_BYTES>>>(
        p_xh, DI, p_xp, DI, p_part, XDBL_W, MROWS, XDBL_W, DI / KSPL,
        DI / KSPL, (size_t)MROWS * XDBL_W, nullptr);
    k3_reduce_kernel<<<MROWS * XDBL_W / 256, 256>>>();

    // K4: delta = softplus(x_dbl[:, :64] . dt_proj_w^T + b)   (4096 x 2048 x 64)
    gemm_h<1><<<dim3(DI / 128, MROWS / 128, 1), 256, SMEM_BYTES>>>(
        p_xdh, XDBL_W, p_dw, DTR, p_delta, DI, MROWS, DI, DTR, 0, 0, dt_proj_b);

    // K5: chunked selective scan (passA -> fixup -> passB)
    scan_passA<<<NCHK * 32768 / 256, 256>>>(A_log);
    scan_fixup<<<32768 / 256, 256>>>();
    scan_passB<<<NCHK * 32768 / 256, 256>>>(A_log, Dp);

    // K6: out = y . out_w^T       (4096 x 1024 x 2048)
    gemm_h<0><<<dim3(DM / 128, MROWS / 128, 1), 256, SMEM_BYTES>>>(
        p_yh, DI, p_ow, DI, out, DM, MROWS, DM, DI, 0, 0, nullptr);
}

// round 9
// speedup vs baseline: 6.5709x; 1.0286x over previous
#include <cuda_runtime.h>
#include <cuda_fp16.h>
#include <math.h>
#include <stdint.h>

// ---------------- problem constants ----------------
#define B_SZ   2
#define SEQ    2048
#define DM     1024
#define DI     2048
#define DS     16
#define DTR    64
#define MROWS  (B_SZ * SEQ)      // 4096
#define E2     (2 * DI)          // 4096
#define XDBL_W 96
#define KSPL   8                 // split-K factor for K3
#define NCHK   8                 // scan chunks
#define CHKL   (SEQ / NCHK)      // 256 steps per chunk
#define NCHAN  (B_SZ * DI)       // 4096

// ---------------- scratch (device globals) ----------------
static __device__ float g_xz   [(size_t)MROWS * E2];
static __device__ float g_xdbl [(size_t)MROWS * XDBL_W];
static __device__ float g_delta[(size_t)MROWS * DI];
static __device__ float g_part [(size_t)KSPL * MROWS * XDBL_W];

// chunked-scan state: per (chunk, chan, sub, state<2>)
static __device__ float g_P   [(size_t)NCHK * NCHAN * 16];
static __device__ float g_hend[(size_t)NCHK * NCHAN * 16];
static __device__ float g_hin [(size_t)NCHK * NCHAN * 16];

static __device__ __half g_hs [(size_t)MROWS * DM];
static __device__ __half g_w1 [(size_t)E2 * DM];
static __device__ __half g_xp [(size_t)128 * DI];      // x_proj padded 96->128 rows
static __device__ __half g_dw [(size_t)DI * DTR];
static __device__ __half g_ow [(size_t)DM * DI];
static __device__ __half g_xh [(size_t)MROWS * DI];    // conv output fp16
static __device__ __half g_xdh[(size_t)MROWS * XDBL_W];// x_dbl fp16
static __device__ __half g_yh [(size_t)MROWS * DI];    // scan output fp16

#define CIX(c, chan, sub) (((((size_t)(c)) * NCHAN + (chan)) * 8 + (sub)) * 2)

// ---------------- tensor-core helpers ----------------
__device__ __forceinline__ void ldsm_x4(uint32_t& r0, uint32_t& r1, uint32_t& r2, uint32_t& r3,
                                        const __half* p)
{
    uint32_t addr = (uint32_t)__cvta_generic_to_shared(p);
    asm volatile("ldmatrix.sync.aligned.m8n8.x4.shared.b16 {%0,%1,%2,%3}, [%4];\n"
                 : "=r"(r0), "=r"(r1), "=r"(r2), "=r"(r3) : "r"(addr));
}

__device__ __forceinline__ void mma_f16(float* c, const uint32_t* a, const uint32_t* b)
{
    asm volatile(
        "mma.sync.aligned.m16n8k16.row.col.f32.f16.f16.f32 "
        "{%0,%1,%2,%3}, {%4,%5,%6,%7}, {%8,%9}, {%0,%1,%2,%3};\n"
        : "+f"(c[0]), "+f"(c[1]), "+f"(c[2]), "+f"(c[3])
        : "r"(a[0]), "r"(a[1]), "r"(a[2]), "r"(a[3]), "r"(b[0]), "r"(b[1]));
}

__device__ __forceinline__ void cp16(void* dst, const void* src)
{
    uint32_t d = (uint32_t)__cvta_generic_to_shared(dst);
    asm volatile("cp.async.cg.shared.global [%0], [%1], 16;\n" :: "r"(d), "l"(src));
}
__device__ __forceinline__ void cp_commit() { asm volatile("cp.async.commit_group;\n"); }
template<int N>
__device__ __forceinline__ void cp_wait()   { asm volatile("cp.async.wait_group %0;\n" :: "n"(N)); }

// ---------------- fused fp32 -> fp16 conversion (single launch) ----------------
#define CN0 (MROWS * DM)     // hs      4194304
#define CN1 (E2 * DM)        // w1      4194304
#define CN2 (DM * DI)        // ow      2097152
#define CN3 (128 * DI)       // xp      262144 (valid 96*DI)
#define CN4 (DI * DTR)       // dw      131072
#define CTOT (CN0 + CN1 + CN2 + CN3 + CN4)

__device__ __forceinline__ void cvt4(const float* __restrict__ s, __half* __restrict__ d,
                                     int idx, int n_valid)
{
    float4 v = make_float4(0.f, 0.f, 0.f, 0.f);
    if (idx < n_valid) v = *reinterpret_cast<const float4*>(s + idx);
    __half h[4];
    h[0] = __float2half_rn(v.x);
    h[1] = __float2half_rn(v.y);
    h[2] = __float2half_rn(v.z);
    h[3] = __float2half_rn(v.w);
    *reinterpret_cast<uint2*>(d + idx) = *reinterpret_cast<uint2*>(h);
}

__global__ void cvt_all(const float* __restrict__ hs, const float* __restrict__ w1,
                        const float* __restrict__ ow, const float* __restrict__ xp,
                        const float* __restrict__ dw)
{
    int i4 = (blockIdx.x * blockDim.x + threadIdx.x) * 4;
    if (i4 < CN0)                       { cvt4(hs, g_hs, i4, CN0); return; }
    i4 -= CN0;
    if (i4 < CN1)                       { cvt4(w1, g_w1, i4, CN1); return; }
    i4 -= CN1;
    if (i4 < CN2)                       { cvt4(ow, g_ow, i4, CN2); return; }
    i4 -= CN2;
    if (i4 < CN3)                       { cvt4(xp, g_xp, i4, 96 * DI); return; }
    i4 -= CN3;
    if (i4 < CN4)                       { cvt4(dw, g_dw, i4, CN4); return; }
}

// ---------------- fp16 HMMA GEMM, 4-stage cp.async, single sync/iter, 2 CTAs/SM -------
#define BK     32
#define LDSMH  40
#define TILEH  (128 * LDSMH)
#define STAGEH (2 * TILEH)
#define NST    4
#define SMEM_BYTES (NST * STAGEH * (int)sizeof(__half))   // 81920

template<int EPI>
__global__ __launch_bounds__(256, 2)
void gemm_h(const __half* __restrict__ A, int lda,
            const __half* __restrict__ B, int ldb,
            float* __restrict__ C, int ldc,
            int M, int N, int K,
            int kzo, size_t czs,
            const float* __restrict__ bias)
{
    extern __shared__ __half smem[];

    const int tid  = threadIdx.x;
    const int lane = tid & 31;
    const int wid  = tid >> 5;
    const int wm   = wid & 3;
    const int wn   = wid >> 2;

    const int bm = blockIdx.y * 128;
    const int bn = blockIdx.x * 128;

    A += (size_t)blockIdx.z * kzo;
    B += (size_t)blockIdx.z * kzo;
    C += (size_t)blockIdx.z * czs;

    const int lrow = tid >> 2;
    const int lslot = (tid & 3) * 8;

    float acc[2][8][4];
#pragma unroll
    for (int i = 0; i < 2; i++)
#pragma unroll
        for (int j = 0; j < 8; j++)
#pragma unroll
            for (int q = 0; q < 4; q++) acc[i][j][q] = 0.f;

    const int KT = K / BK;

    auto load_stage = [&](int s, int kt) {
        __half* sA = smem + s * STAGEH;
        __half* sB = sA + TILEH;
        int k0 = kt * BK;
#pragma unroll
        for (int p = 0; p < 2; p++) {
            int r = lrow + p * 64;
            cp16(sA + r * LDSMH + lslot, A + (size_t)(bm + r) * lda + k0 + lslot);
            cp16(sB + r * LDSMH + lslot, B + (size_t)(bn + r) * ldb + k0 + lslot);
        }
    };

    load_stage(0, 0);
    cp_commit();
    if (KT > 1) { load_stage(1, 1); cp_commit(); }

    for (int it = 0; it < KT; it++) {
        if (it + 2 < KT) {
            load_stage((it + 2) % NST, it + 2);
            cp_commit();
            cp_wait<2>();
        } else if (it + 1 < KT) {
            cp_wait<1>();
        } else {
            cp_wait<0>();
        }
        __syncthreads();          // single barrier per iter (safe with NST=4, dist-2)

        const __half* sA = smem + (it % NST) * STAGEH;
        const __half* sB = sA + TILEH;

        uint32_t af[2][2][4], bf[2][8][2];

        auto ldf = [&](int q, int ks) {
            int arow_off = lane & 15;
            int akc = ks * 16 + (lane >> 4) * 8;
#pragma unroll
            for (int mt = 0; mt < 2; mt++) {
                int arow = wm * 32 + mt * 16 + arow_off;
                ldsm_x4(af[q][mt][0], af[q][mt][1], af[q][mt][2], af[q][mt][3],
                        sA + arow * LDSMH + akc);
            }
            int nrow_off = (lane & 7) + ((lane >> 4) & 1) * 8;
            int bkc = ks * 16 + ((lane >> 3) & 1) * 8;
#pragma unroll
            for (int ntp = 0; ntp < 4; ntp++) {
                int nrow = wn * 64 + ntp * 16 + nrow_off;
                ldsm_x4(bf[q][2 * ntp][0], bf[q][2 * ntp][1],
                        bf[q][2 * ntp + 1][0], bf[q][2 * ntp + 1][1],
                        sB + nrow * LDSMH + bkc);
            }
        };

        ldf(0, 0);
#pragma unroll
        for (int ks = 0; ks < 2; ks++) {
            if (ks == 0) ldf(1, 1);
#pragma unroll
            for (int mt = 0; mt < 2; mt++)
#pragma unroll
                for (int nt = 0; nt < 8; nt++)
                    mma_f16(acc[mt][nt], af[ks][mt], bf[ks][nt]);
        }
    }

#pragma unroll
    for (int mt = 0; mt < 2; mt++) {
        int row = bm + wm * 32 + mt * 16 + (lane >> 2);
#pragma unroll
        for (int nt = 0; nt < 8; nt++) {
            int col = bn + wn * 64 + nt * 8 + (lane & 3) * 2;
            if (col >= N) continue;
#pragma unroll
            for (int half_ = 0; half_ < 2; half_++) {
                int r = row + half_ * 8;
                float v0 = acc[mt][nt][2 * half_ + 0];
                float v1 = acc[mt][nt][2 * half_ + 1];
                if (EPI == 1) {
                    v0 += bias[col];
                    v1 += bias[col + 1];
                    v0 = (v0 > 20.f) ? v0 : log1pf(expf(v0));
                    v1 = (v1 > 20.f) ? v1 : log1pf(expf(v1));
                }
                float2 st; st.x = v0; st.y = v1;
                *reinterpret_cast<float2*>(C + (size_t)r * ldc + col) = st;
            }
        }
    }
}

// ---------------- K3 split-K reduce ----------------
__global__ void k3_reduce_kernel()
{
    int i = blockIdx.x * blockDim.x + threadIdx.x;
    float s = 0.f;
#pragma unroll
    for (int z = 0; z < KSPL; z++)
        s += g_part[(size_t)z * MROWS * XDBL_W + i];
    g_xdbl[i] = s;
    g_xdh[i] = __float2half_rn(s);
}

// ---------------- depthwise conv + bias + silu; fp16 output only ----------------
__global__ void conv_silu_kernel(const float* __restrict__ cw,
                                 const float* __restrict__ cb)
{
    int d = blockIdx.x * blockDim.x + threadIdx.x;
    int m = blockIdx.y;
    int l = m & (SEQ - 1);

    float acc = cb[d];
#pragma unroll
    for (int k = 0; k < 4; k++) {
        int ll = l - 3 + k;
        if (ll >= 0)
            acc = fmaf(cw[d * 4 + k], g_xz[(size_t)(m - 3 + k) * E2 + d], acc);
    }
    float s = acc / (1.f + expf(-acc));
    g_xh[(size_t)m * DI + d] = __float2half_rn(s);
}

// ---------------- chunked selective scan ----------------
// Pass A: per (chunk, chan, sub): decay product P and chunk-local end state (h from 0).
__global__ void scan_passA(const float* __restrict__ A_log)
{
    int t = blockIdx.x * blockDim.x + threadIdx.x;
    int chunk = t >> 15;
    int r = t & 32767;
    int chan = r >> 3;
    int sub  = r & 7;
    int b = chan >> 11;
    int d = chan & (DI - 1);

    float A0 = -expf(A_log[d * DS + sub * 2 + 0]);
    float A1 = -expf(A_log[d * DS + sub * 2 + 1]);

    float h0 = 0.f, h1 = 0.f, P0 = 1.f, P1 = 1.f;
    size_t mb = (size_t)b * SEQ + chunk * CHKL;

    float dt = g_delta[mb * DI + d];
    float xv = __half2float(g_xh[mb * DI + d]);
    float2 Bv = *reinterpret_cast<const float2*>(g_xdbl + mb * XDBL_W + DTR + sub * 2);

    for (int l = 0; l < CHKL; l++) {
        float dtn = 0.f, xvn = 0.f;
        float2 Bn = make_float2(0.f, 0.f);
        if (l + 1 < CHKL) {
            size_t m2 = mb + l + 1;
            dtn = g_delta[m2 * DI + d];
            xvn = __half2float(g_xh[m2 * DI + d]);
            Bn = *reinterpret_cast<const float2*>(g_xdbl + m2 * XDBL_W + DTR + sub * 2);
        }
        float dx = dt * xv;
        float e0 = __expf(dt * A0);
        float e1 = __expf(dt * A1);
        P0 *= e0;
        P1 *= e1;
        h0 = fmaf(e0, h0, dx * Bv.x);
        h1 = fmaf(e1, h1, dx * Bv.y);
        dt = dtn; xv = xvn; Bv = Bn;
    }

    size_t o = CIX(chunk, chan, sub);
    g_P[o]     = P0;  g_P[o + 1]    = P1;
    g_hend[o]  = h0;  g_hend[o + 1] = h1;
}

// Fix-up: serial compose over chunks (parallel over chan x sub).
__global__ void scan_fixup()
{
    int t = blockIdx.x * blockDim.x + threadIdx.x;
    int chan = t >> 3;
    int sub  = t & 7;

    float h0 = 0.f, h1 = 0.f;
    {
        size_t o = CIX(0, chan, sub);
        g_hin[o] = 0.f; g_hin[o + 1] = 0.f;
    }
#pragma unroll
    for (int c = 1; c < NCHK; c++) {
        size_t p = CIX(c - 1, chan, sub);
        h0 = fmaf(g_P[p],     h0, g_hend[p]);
        h1 = fmaf(g_P[p + 1], h1, g_hend[p + 1]);
        size_t o = CIX(c, chan, sub);
        g_hin[o] = h0; g_hin[o + 1] = h1;
    }
}

// Pass B: full scan per chunk seeded with h_in; emits gated y (fp16).
__global__ void scan_passB(const float* __restrict__ A_log,
                           const float* __restrict__ Dp)
{
    int t = blockIdx.x * blockDim.x + threadIdx.x;
    int chunk = t >> 15;
    int r = t & 32767;
    int chan = r >> 3;
    int sub  = r & 7;
    int b = chan >> 11;
    int d = chan & (DI - 1);

    float A0 = -expf(A_log[d * DS + sub * 2 + 0]);
    float A1 = -expf(A_log[d * DS + sub * 2 + 1]);
    float Dd = Dp[d];

    float h0, h1;
    {
        size_t o = CIX(chunk, chan, sub);
        h0 = g_hin[o]; h1 = g_hin[o + 1];
    }
    size_t mb = (size_t)b * SEQ + chunk * CHKL;

    float dt = g_delta[mb * DI + d];
    float xv = __half2float(g_xh[mb * DI + d]);
    float zv = g_xz[mb * E2 + DI + d];
    float2 Bv = *reinterpret_cast<const float2*>(g_xdbl + mb * XDBL_W + DTR + sub * 2);
    float2 Cv = *reinterpret_cast<const float2*>(g_xdbl + mb * XDBL_W + DTR + DS + sub * 2);

    for (int l = 0; l < CHKL; l++) {
        float dtn = 0.f, xvn = 0.f, zvn = 0.f;
        float2 Bn = make_float2(0.f, 0.f), Cn = Bn;
        if (l + 1 < CHKL) {
            size_t m2 = mb + l + 1;
            dtn = g_delta[m2 * DI + d];
            xvn = __half2float(g_xh[m2 * DI + d]);
            zvn = g_xz[m2 * E2 + DI + d];
            Bn = *reinterpret_cast<const float2*>(g_xdbl + m2 * XDBL_W + DTR + sub * 2);
            Cn = *reinterpret_cast<const float2*>(g_xdbl + m2 * XDBL_W + DTR + DS + sub * 2);
        }

        float dx = dt * xv;
        float e0 = __expf(dt * A0);
        float e1 = __expf(dt * A1);
        h0 = fmaf(e0, h0, dx * Bv.x);
        h1 = fmaf(e1, h1, dx * Bv.y);
        float part = fmaf(h1, Cv.y, h0 * Cv.x);
        part += __shfl_xor_sync(0xFFFFFFFFu, part, 1);
        part += __shfl_xor_sync(0xFFFFFFFFu, part, 2);
        part += __shfl_xor_sync(0xFFFFFFFFu, part, 4);

        if (sub == 0) {
            float sz = zv / (1.f + __expf(-zv));
            float yv = (part + Dd * xv) * sz;
            g_yh[(mb + l) * DI + d] = __float2half_rn(yv);
        }

        dt = dtn; xv = xvn; zv = zvn; Bv = Bn; Cv = Cn;
    }
}

// ---------------- launch ----------------
extern "C" void kernel_launch(void* const* d_in, const int* in_sizes, int n_in,
                              void* d_out, int out_size)
{
    const float* hs        = (const float*)d_in[0];
    const float* in_proj_w = (const float*)d_in[1];
    const float* conv_w    = (const float*)d_in[2];
    const float* conv_b    = (const float*)d_in[3];
    const float* x_proj_w  = (const float*)d_in[4];
    const float* dt_proj_w = (const float*)d_in[5];
    const float* dt_proj_b = (const float*)d_in[6];
    const float* A_log     = (const float*)d_in[7];
    const float* Dp        = (const float*)d_in[8];
    const float* out_w     = (const float*)d_in[9];
    float* out = (float*)d_out;

    float *p_xz, *p_part, *p_delta;
    cudaGetSymbolAddress((void**)&p_xz,    g_xz);
    cudaGetSymbolAddress((void**)&p_part,  g_part);
    cudaGetSymbolAddress((void**)&p_delta, g_delta);

    __half *p_hs, *p_w1, *p_xp, *p_dw, *p_ow, *p_xh, *p_xdh, *p_yh;
    cudaGetSymbolAddress((void**)&p_hs,  g_hs);
    cudaGetSymbolAddress((void**)&p_w1,  g_w1);
    cudaGetSymbolAddress((void**)&p_xp,  g_xp);
    cudaGetSymbolAddress((void**)&p_dw,  g_dw);
    cudaGetSymbolAddress((void**)&p_ow,  g_ow);
    cudaGetSymbolAddress((void**)&p_xh,  g_xh);
    cudaGetSymbolAddress((void**)&p_xdh, g_xdh);
    cudaGetSymbolAddress((void**)&p_yh,  g_yh);

    cudaFuncSetAttribute(gemm_h<0>, cudaFuncAttributeMaxDynamicSharedMemorySize, SMEM_BYTES);
    cudaFuncSetAttribute(gemm_h<1>, cudaFuncAttributeMaxDynamicSharedMemorySize, SMEM_BYTES);

    // C0: all conversions in one launch
    cvt_all<<<CTOT / 4 / 256, 256>>>(hs, in_proj_w, out_w, x_proj_w, dt_proj_w);

    // K1: xz = hs . in_proj_w^T   (4096 x 4096 x 1024)
    gemm_h<0><<<dim3(E2 / 128, MROWS / 128, 1), 256, SMEM_BYTES>>>(
        p_hs, DM, p_w1, DM, p_xz, E2, MROWS, E2, DM, 0, 0, nullptr);

    // K2: depthwise conv + bias + silu
    conv_silu_kernel<<<dim3(DI / 256, MROWS), 256>>>(conv_w, conv_b);

    // K3: x_dbl partials = x . x_proj_w^T  (4096 x 96 x 2048), split-K x8
    gemm_h<0><<<dim3(1, MROWS / 128, KSPL), 256, SMEM_BYTES>>>(
        p_xh, DI, p_xp, DI, p_part, XDBL_W, MROWS, XDBL_W, DI / KSPL,
        DI / KSPL, (size_t)MROWS * XDBL_W, nullptr);
    k3_reduce_kernel<<<MROWS * XDBL_W / 256, 256>>>();

    // K4: delta = softplus(x_dbl[:, :64] . dt_proj_w^T + b)   (4096 x 2048 x 64)
    gemm_h<1><<<dim3(DI / 128, MROWS / 128, 1), 256, SMEM_BYTES>>>(
        p_xdh, XDBL_W, p_dw, DTR, p_delta, DI, MROWS, DI, DTR, 0, 0, dt_proj_b);

    // K5: chunked selective scan (passA -> fixup -> passB)
    scan_passA<<<NCHK * 32768 / 256, 256>>>(A_log);
    scan_fixup<<<32768 / 256, 256>>>();
    scan_passB<<<NCHK * 32768 / 256, 256>>>(A_log, Dp);

    // K6: out = y . out_w^T       (4096 x 1024 x 2048)
    gemm_h<0><<<dim3(DM / 128, MROWS / 128, 1), 256, SMEM_BYTES>>>(
        p_yh, DI, p_ow, DI, out, DM, MROWS, DM, DI, 0, 0, nullptr);
}